// round 3
// baseline (speedup 1.0000x reference)
#include <cuda_runtime.h>
#include <math.h>

#define NB 8
#define NF 4096
#define NQ 64
#define ND 1024
#define NH 16
#define DHD 64
#define NFL 4160          // NF + NQ
#define INNER 1024

// ---------------- scratch (device globals; no allocation allowed) ----------
__device__ float g_xln[34078720];   // (B, FL, D)  = 8*4160*1024
__device__ float g_lat[524288];     // (B, Q, D)   LN(latents), contiguous
__device__ float g_q[524288];       // (B, Q, inner) scaled by 1/8
__device__ float g_k[34078720];     // (B, FL, inner)
__device__ float g_v[34078720];     // (B, FL, inner)
__device__ float g_attn[524288];    // (B, Q, inner)

// ---------------- LayerNorm of [features ; latents] ------------------------
__global__ __launch_bounds__(256) void ln_kernel(
    const float* __restrict__ feat, const float* __restrict__ lat,
    const float* __restrict__ lnm_w, const float* __restrict__ lnm_b,
    const float* __restrict__ lnl_w, const float* __restrict__ lnl_b)
{
    int r = blockIdx.x;                 // 0 .. B*FL-1
    int b = r / NFL, f = r - b * NFL;
    const float* src; const float* w; const float* bias;
    float* dst2 = nullptr;
    if (f < NF) {
        src = feat + (size_t)(b * NF + f) * ND; w = lnm_w; bias = lnm_b;
    } else {
        int q = f - NF;
        src = lat + (size_t)(b * NQ + q) * ND; w = lnl_w; bias = lnl_b;
        dst2 = g_lat + (size_t)(b * NQ + q) * ND;
    }
    float* dst = g_xln + (size_t)r * ND;

    int t = threadIdx.x;                // 256 threads, 1 float4 each (D=1024)
    float4 v = ((const float4*)src)[t];
    float s  = v.x + v.y + v.z + v.w;
    float ss = v.x*v.x + v.y*v.y + v.z*v.z + v.w*v.w;

    __shared__ float red[2][8];
    __shared__ float stat[2];
    #pragma unroll
    for (int o = 16; o > 0; o >>= 1) {
        s  += __shfl_down_sync(0xffffffffu, s,  o);
        ss += __shfl_down_sync(0xffffffffu, ss, o);
    }
    int wid = t >> 5, lid = t & 31;
    if (lid == 0) { red[0][wid] = s; red[1][wid] = ss; }
    __syncthreads();
    if (t == 0) {
        float a = 0.f, c = 0.f;
        #pragma unroll
        for (int i = 0; i < 8; i++) { a += red[0][i]; c += red[1][i]; }
        float mu  = a * (1.0f / ND);
        float var = c * (1.0f / ND) - mu * mu;
        stat[0] = mu; stat[1] = rsqrtf(var + 1e-5f);
    }
    __syncthreads();
    float mu = stat[0], inv = stat[1];
    float4 w4 = ((const float4*)w)[t];
    float4 b4 = ((const float4*)bias)[t];
    float4 o;
    o.x = (v.x - mu) * inv * w4.x + b4.x;
    o.y = (v.y - mu) * inv * w4.y + b4.y;
    o.z = (v.z - mu) * inv * w4.z + b4.z;
    o.w = (v.w - mu) * inv * w4.w + b4.w;
    ((float4*)dst)[t] = o;
    if (dst2) ((float4*)dst2)[t] = o;
}

// ---------------- fp32 SGEMM: C[M,N] = alpha * A[M,K] @ B[K,N] -------------
// 128x128 tile, BK=16, 256 threads, 8x8 microtile, register prefetch.
__global__ __launch_bounds__(256, 2) void sgemm_kernel(
    const float* __restrict__ A, const float* __restrict__ Bw,
    float* __restrict__ C, int M, int N, int K, float alpha)
{
    __shared__ float As[16][128];
    __shared__ float Bs[16][128];
    int tid = threadIdx.x;
    int tx = tid & 15, ty = tid >> 4;
    int bm = blockIdx.y * 128;
    int bn = blockIdx.x * 128;

    int a_row = tid >> 1;            // 0..127
    int a_k   = (tid & 1) * 8;       // 0 or 8
    int b_k   = tid >> 5;            // 0..7 (plus +8)
    int b_n   = (tid & 31) * 4;

    const float* Ap = A  + (size_t)(bm + a_row) * K + a_k;
    const float* Bp = Bw + (size_t)b_k * N + bn + b_n;

    float4 pa0 = *(const float4*)(Ap);
    float4 pa1 = *(const float4*)(Ap + 4);
    float4 pb0 = *(const float4*)(Bp);
    float4 pb1 = *(const float4*)(Bp + 8 * (size_t)N);

    float acc[8][8];
    #pragma unroll
    for (int i = 0; i < 8; i++)
        #pragma unroll
        for (int j = 0; j < 8; j++) acc[i][j] = 0.f;

    int ktiles = K >> 4;
    for (int kt = 0; kt < ktiles; ++kt) {
        As[a_k+0][a_row] = pa0.x; As[a_k+1][a_row] = pa0.y;
        As[a_k+2][a_row] = pa0.z; As[a_k+3][a_row] = pa0.w;
        As[a_k+4][a_row] = pa1.x; As[a_k+5][a_row] = pa1.y;
        As[a_k+6][a_row] = pa1.z; As[a_k+7][a_row] = pa1.w;
        *(float4*)&Bs[b_k][b_n]     = pb0;
        *(float4*)&Bs[b_k + 8][b_n] = pb1;
        __syncthreads();
        if (kt + 1 < ktiles) {
            const float* Ap2 = Ap + (kt + 1) * 16;
            const float* Bp2 = Bp + (size_t)(kt + 1) * 16 * N;
            pa0 = *(const float4*)(Ap2);
            pa1 = *(const float4*)(Ap2 + 4);
            pb0 = *(const float4*)(Bp2);
            pb1 = *(const float4*)(Bp2 + 8 * (size_t)N);
        }
        #pragma unroll
        for (int kk = 0; kk < 16; ++kk) {
            float4 ra0 = *(const float4*)&As[kk][ty * 8];
            float4 ra1 = *(const float4*)&As[kk][ty * 8 + 4];
            float4 rb0 = *(const float4*)&Bs[kk][tx * 8];
            float4 rb1 = *(const float4*)&Bs[kk][tx * 8 + 4];
            float ar[8] = {ra0.x, ra0.y, ra0.z, ra0.w, ra1.x, ra1.y, ra1.z, ra1.w};
            float br[8] = {rb0.x, rb0.y, rb0.z, rb0.w, rb1.x, rb1.y, rb1.z, rb1.w};
            #pragma unroll
            for (int i = 0; i < 8; i++)
                #pragma unroll
                for (int j = 0; j < 8; j++)
                    acc[i][j] += ar[i] * br[j];
        }
        __syncthreads();
    }
    #pragma unroll
    for (int i = 0; i < 8; i++) {
        float* crow = C + (size_t)(bm + ty * 8 + i) * N + bn + tx * 8;
        float4 o0 = make_float4(alpha*acc[i][0], alpha*acc[i][1], alpha*acc[i][2], alpha*acc[i][3]);
        float4 o1 = make_float4(alpha*acc[i][4], alpha*acc[i][5], alpha*acc[i][6], alpha*acc[i][7]);
        *(float4*)(crow)     = o0;
        *(float4*)(crow + 4) = o1;
    }
}

// ---------------- Flash attention: one block per (b, h) --------------------
#define CH 64            // key chunk
#define SMP 68           // padded smem row stride (floats)
#define ATTN_SMEM ((4 * 64 * SMP + 3 * 64) * 4)

__global__ __launch_bounds__(256) void attn_kernel()
{
    extern __shared__ float sm[];
    float* qs   = sm;                   // [64][SMP]
    float* ks   = qs + 64 * SMP;        // [64][SMP]
    float* vs   = ks + 64 * SMP;        // [64][SMP]
    float* ps   = vs + 64 * SMP;        // [64][SMP]
    float* mrow = ps + 64 * SMP;        // [64]
    float* lrow = mrow + 64;
    float* srow = lrow + 64;

    int tid = threadIdx.x;
    int bh = blockIdx.x;
    int b = bh >> 4, h = bh & 15;

    // stage q (already scaled by 1/8 in g_q)
    {
        const float* qbase = g_q + (size_t)(b * NQ) * INNER + h * DHD;
        #pragma unroll
        for (int t = 0; t < 4; t++) {
            int fi = tid + t * 256;               // 0..1023 float4s
            int row = fi >> 4, c4 = (fi & 15) * 4;
            float4 v = *(const float4*)(qbase + (size_t)row * INNER + c4);
            *(float4*)&qs[row * SMP + c4] = v;
        }
    }
    if (tid < 64) { mrow[tid] = -1e30f; lrow[tid] = 0.f; }

    const float* kbase = g_k + (size_t)(b * NFL) * INNER + h * DHD;
    const float* vbase = g_v + (size_t)(b * NFL) * INNER + h * DHD;

    int q0 = (tid >> 4) * 4;     // 4 q rows
    int k0 = tid & 15;           // keys k0 + 16*j
    int v0 = (tid & 15) * 4;     // 4 v columns

    float o[4][4];
    #pragma unroll
    for (int i = 0; i < 4; i++)
        #pragma unroll
        for (int j = 0; j < 4; j++) o[i][j] = 0.f;

    // prefetch chunk 0
    float4 kf[4], vf[4];
    #pragma unroll
    for (int t = 0; t < 4; t++) {
        int fi = tid + t * 256;
        int row = fi >> 4, c4 = (fi & 15) * 4;
        kf[t] = *(const float4*)(kbase + (size_t)row * INNER + c4);
        vf[t] = *(const float4*)(vbase + (size_t)row * INNER + c4);
    }

    const int NCHK = NFL / CH;   // 65
    for (int c = 0; c < NCHK; ++c) {
        __syncthreads();         // prior chunk fully consumed (covers q-stage at c=0)
        #pragma unroll
        for (int t = 0; t < 4; t++) {
            int fi = tid + t * 256;
            int row = fi >> 4, c4 = (fi & 15) * 4;
            *(float4*)&ks[row * SMP + c4] = kf[t];
            *(float4*)&vs[row * SMP + c4] = vf[t];
        }
        __syncthreads();
        if (c + 1 < NCHK) {      // prefetch next chunk (overlaps compute)
            size_t off = (size_t)(c + 1) * CH * INNER;
            #pragma unroll
            for (int t = 0; t < 4; t++) {
                int fi = tid + t * 256;
                int row = fi >> 4, c4 = (fi & 15) * 4;
                kf[t] = *(const float4*)(kbase + off + (size_t)row * INNER + c4);
                vf[t] = *(const float4*)(vbase + off + (size_t)row * INNER + c4);
            }
        }
        // ---- S = q @ k^T  (thread: q rows q0..q0+3 x keys k0+16j) ----
        float s[4][4];
        #pragma unroll
        for (int i = 0; i < 4; i++)
            #pragma unroll
            for (int j = 0; j < 4; j++) s[i][j] = 0.f;
        #pragma unroll
        for (int d = 0; d < 64; d += 4) {
            float4 qa[4], ka[4];
            #pragma unroll
            for (int i = 0; i < 4; i++) qa[i] = *(const float4*)&qs[(q0 + i) * SMP + d];
            #pragma unroll
            for (int j = 0; j < 4; j++) ka[j] = *(const float4*)&ks[(k0 + j * 16) * SMP + d];
            #pragma unroll
            for (int i = 0; i < 4; i++)
                #pragma unroll
                for (int j = 0; j < 4; j++)
                    s[i][j] += qa[i].x * ka[j].x + qa[i].y * ka[j].y +
                               qa[i].z * ka[j].z + qa[i].w * ka[j].w;
        }
        #pragma unroll
        for (int i = 0; i < 4; i++)
            #pragma unroll
            for (int j = 0; j < 4; j++)
                ps[(q0 + i) * SMP + k0 + j * 16] = s[i][j];
        __syncthreads();
        // ---- online softmax (4 threads per row, warp shuffles) ----
        {
            int row = tid >> 2;
            int j0  = (tid & 3) * 16;
            float* prow = ps + row * SMP + j0;
            float pv[16];
            float cmax = -1e30f;
            #pragma unroll
            for (int j = 0; j < 16; j++) { pv[j] = prow[j]; cmax = fmaxf(cmax, pv[j]); }
            cmax = fmaxf(cmax, __shfl_xor_sync(0xffffffffu, cmax, 1));
            cmax = fmaxf(cmax, __shfl_xor_sync(0xffffffffu, cmax, 2));
            float mold = mrow[row];
            float mnew = fmaxf(mold, cmax);
            float sum = 0.f;
            #pragma unroll
            for (int j = 0; j < 16; j++) { pv[j] = __expf(pv[j] - mnew); sum += pv[j]; }
            sum += __shfl_xor_sync(0xffffffffu, sum, 1);
            sum += __shfl_xor_sync(0xffffffffu, sum, 2);
            #pragma unroll
            for (int j = 0; j < 16; j++) prow[j] = pv[j];
            if ((tid & 3) == 0) {
                float sc = __expf(mold - mnew);
                srow[row] = sc;
                lrow[row] = lrow[row] * sc + sum;
                mrow[row] = mnew;
            }
        }
        __syncthreads();
        // ---- rescale + O += P @ V ----
        #pragma unroll
        for (int i = 0; i < 4; i++) {
            float sc = srow[q0 + i];
            #pragma unroll
            for (int j = 0; j < 4; j++) o[i][j] *= sc;
        }
        #pragma unroll
        for (int j4 = 0; j4 < 16; ++j4) {
            float4 pa[4], va[4];
            #pragma unroll
            for (int i = 0; i < 4; i++) pa[i] = *(const float4*)&ps[(q0 + i) * SMP + j4 * 4];
            #pragma unroll
            for (int l = 0; l < 4; l++) va[l] = *(const float4*)&vs[(j4 * 4 + l) * SMP + v0];
            #pragma unroll
            for (int i = 0; i < 4; i++) {
                o[i][0] += pa[i].x * va[0].x + pa[i].y * va[1].x + pa[i].z * va[2].x + pa[i].w * va[3].x;
                o[i][1] += pa[i].x * va[0].y + pa[i].y * va[1].y + pa[i].z * va[2].y + pa[i].w * va[3].y;
                o[i][2] += pa[i].x * va[0].z + pa[i].y * va[1].z + pa[i].z * va[2].z + pa[i].w * va[3].z;
                o[i][3] += pa[i].x * va[0].w + pa[i].y * va[1].w + pa[i].z * va[2].w + pa[i].w * va[3].w;
            }
        }
    }
    // ---- finalize: divide by l, write (B, Q, H*dh) ----
    #pragma unroll
    for (int i = 0; i < 4; i++) {
        float inv = 1.0f / lrow[q0 + i];
        float4 ov = make_float4(o[i][0] * inv, o[i][1] * inv, o[i][2] * inv, o[i][3] * inv);
        *(float4*)&g_attn[(size_t)(b * NQ + q0 + i) * INNER + h * DHD + v0] = ov;
    }
}

// ---------------- launcher -------------------------------------------------
extern "C" void kernel_launch(void* const* d_in, const int* in_sizes, int n_in,
                              void* d_out, int out_size)
{
    const float* features = (const float*)d_in[0];
    const float* latents  = (const float*)d_in[1];
    const float* lnm_w    = (const float*)d_in[2];
    const float* lnm_b    = (const float*)d_in[3];
    const float* lnl_w    = (const float*)d_in[4];
    const float* lnl_b    = (const float*)d_in[5];
    const float* Wq       = (const float*)d_in[6];
    const float* Wk       = (const float*)d_in[7];
    const float* Wv       = (const float*)d_in[8];
    const float* Wo       = (const float*)d_in[9];
    float* out = (float*)d_out;

    float *p_xln, *p_lat, *p_q, *p_k, *p_v, *p_attn;
    cudaGetSymbolAddress((void**)&p_xln,  g_xln);
    cudaGetSymbolAddress((void**)&p_lat,  g_lat);
    cudaGetSymbolAddress((void**)&p_q,    g_q);
    cudaGetSymbolAddress((void**)&p_k,    g_k);
    cudaGetSymbolAddress((void**)&p_v,    g_v);
    cudaGetSymbolAddress((void**)&p_attn, g_attn);

    // 1) LayerNorm of features and latents into concatenated buffer
    ln_kernel<<<NB * NFL, 256>>>(features, latents, lnm_w, lnm_b, lnl_w, lnl_b);

    // 2) K / V projections: (33280 x 1024) @ (1024 x 1024)
    dim3 gKV(1024 / 128, (NB * NFL) / 128);   // (8, 260)
    sgemm_kernel<<<gKV, 256>>>(p_xln, Wk, p_k, NB * NFL, 1024, 1024, 1.0f);
    sgemm_kernel<<<gKV, 256>>>(p_xln, Wv, p_v, NB * NFL, 1024, 1024, 1.0f);

    // 3) q projection with 1/sqrt(dh) folded in
    dim3 gQ(1024 / 128, (NB * NQ) / 128);     // (8, 4)
    sgemm_kernel<<<gQ, 256>>>(p_lat, Wq, p_q, NB * NQ, 1024, 1024, 0.125f);

    // 4) attention: one block per (b, h)
    cudaFuncSetAttribute(attn_kernel, cudaFuncAttributeMaxDynamicSharedMemorySize, ATTN_SMEM);
    attn_kernel<<<NB * NH, 256, ATTN_SMEM>>>();

    // 5) output projection
    sgemm_kernel<<<gQ, 256>>>(p_attn, Wo, out, NB * NQ, 1024, 1024, 1.0f);
}

// round 5
// speedup vs baseline: 2.0645x; 2.0645x over previous
#include <cuda_runtime.h>
#include <cuda_bf16.h>
#include <math.h>
#include <stdint.h>

#define NB 8
#define NF 4096
#define NQ 64
#define ND 1024
#define NH 16
#define DHD 64
#define NFL 4160            // NF + NQ
#define INNER 1024
#define MKV (NB*NFL)        // 33280
#define MQ  (NB*NQ)         // 512

// ---------------- scratch (device globals; no allocation allowed) ----------
__device__ __nv_bfloat16 g_xh[34078720];    // LN([feat;lat]) hi  (B,FL,D)
__device__ __nv_bfloat16 g_xl[34078720];    // LN([feat;lat]) lo
__device__ __nv_bfloat16 g_lath[524288];    // LN(latents) hi, contiguous (B,Q,D)
__device__ __nv_bfloat16 g_latl[524288];
__device__ __nv_bfloat16 g_wqh[1048576], g_wql[1048576];   // W^T hi/lo  [N,K]
__device__ __nv_bfloat16 g_wkh[1048576], g_wkl[1048576];
__device__ __nv_bfloat16 g_wvh[1048576], g_wvl[1048576];
__device__ __nv_bfloat16 g_woh[1048576], g_wol[1048576];
__device__ float g_q[524288];               // (B,Q,inner) scaled 1/8
__device__ float g_k[34078720];             // (B,FL,inner) fp32
__device__ float g_v[34078720];
__device__ float g_opart[2097152];          // 128 bh * 4 splits * 64 * 64
__device__ float g_mpart[32768];            // 128*4*64
__device__ float g_lpart[32768];
__device__ __nv_bfloat16 g_ah[524288];      // attn out hi/lo (B,Q,inner)
__device__ __nv_bfloat16 g_al[524288];

// ==================== helpers ==============================================
__device__ __forceinline__ uint32_t smem_u32(const void* p) {
    uint32_t a;
    asm("{ .reg .u64 t; cvta.to.shared.u64 t, %1; cvt.u32.u64 %0, t; }" : "=r"(a) : "l"(p));
    return a;
}
__device__ __forceinline__ void ldm_x4(uint32_t* r, uint32_t addr) {
    asm volatile("ldmatrix.sync.aligned.m8n8.x4.shared.b16 {%0,%1,%2,%3}, [%4];"
                 : "=r"(r[0]), "=r"(r[1]), "=r"(r[2]), "=r"(r[3]) : "r"(addr));
}
__device__ __forceinline__ void ldm_x2(uint32_t* r, uint32_t addr) {
    asm volatile("ldmatrix.sync.aligned.m8n8.x2.shared.b16 {%0,%1}, [%2];"
                 : "=r"(r[0]), "=r"(r[1]) : "r"(addr));
}
__device__ __forceinline__ void mma_bf16(float* c, const uint32_t* a, const uint32_t* b) {
    asm volatile("mma.sync.aligned.m16n8k16.row.col.f32.bf16.bf16.f32 "
                 "{%0,%1,%2,%3}, {%4,%5,%6,%7}, {%8,%9}, {%0,%1,%2,%3};"
                 : "+f"(c[0]), "+f"(c[1]), "+f"(c[2]), "+f"(c[3])
                 : "r"(a[0]), "r"(a[1]), "r"(a[2]), "r"(a[3]), "r"(b[0]), "r"(b[1]));
}

// ==================== LayerNorm -> bf16 hi/lo ==============================
__global__ __launch_bounds__(256) void ln_kernel(
    const float* __restrict__ feat, const float* __restrict__ lat,
    const float* __restrict__ lnm_w, const float* __restrict__ lnm_b,
    const float* __restrict__ lnl_w, const float* __restrict__ lnl_b)
{
    int r = blockIdx.x;
    int b = r / NFL, f = r - b * NFL;
    const float* src; const float* w; const float* bias;
    bool is_lat = (f >= NF);
    int ql = 0;
    if (!is_lat) { src = feat + (size_t)(b * NF + f) * ND; w = lnm_w; bias = lnm_b; }
    else { ql = f - NF; src = lat + (size_t)(b * NQ + ql) * ND; w = lnl_w; bias = lnl_b; }

    int t = threadIdx.x;
    float4 v = ((const float4*)src)[t];
    float s  = v.x + v.y + v.z + v.w;
    float ss = v.x*v.x + v.y*v.y + v.z*v.z + v.w*v.w;

    __shared__ float red[2][8];
    __shared__ float stat[2];
    #pragma unroll
    for (int o = 16; o > 0; o >>= 1) {
        s  += __shfl_down_sync(0xffffffffu, s,  o);
        ss += __shfl_down_sync(0xffffffffu, ss, o);
    }
    int wid = t >> 5, lid = t & 31;
    if (lid == 0) { red[0][wid] = s; red[1][wid] = ss; }
    __syncthreads();
    if (t == 0) {
        float a = 0.f, c = 0.f;
        #pragma unroll
        for (int i = 0; i < 8; i++) { a += red[0][i]; c += red[1][i]; }
        float mu  = a * (1.0f / ND);
        float var = c * (1.0f / ND) - mu * mu;
        stat[0] = mu; stat[1] = rsqrtf(var + 1e-5f);
    }
    __syncthreads();
    float mu = stat[0], inv = stat[1];
    float4 w4 = ((const float4*)w)[t];
    float4 b4 = ((const float4*)bias)[t];
    float o0 = (v.x - mu) * inv * w4.x + b4.x;
    float o1 = (v.y - mu) * inv * w4.y + b4.y;
    float o2 = (v.z - mu) * inv * w4.z + b4.z;
    float o3 = (v.w - mu) * inv * w4.w + b4.w;

    __nv_bfloat16 h0 = __float2bfloat16(o0), h1 = __float2bfloat16(o1);
    __nv_bfloat16 h2 = __float2bfloat16(o2), h3 = __float2bfloat16(o3);
    __nv_bfloat16 l0 = __float2bfloat16(o0 - __bfloat162float(h0));
    __nv_bfloat16 l1 = __float2bfloat16(o1 - __bfloat162float(h1));
    __nv_bfloat16 l2 = __float2bfloat16(o2 - __bfloat162float(h2));
    __nv_bfloat16 l3 = __float2bfloat16(o3 - __bfloat162float(h3));

    size_t idx = (size_t)r * ND + t * 4;
    *(__nv_bfloat162*)&g_xh[idx]     = __nv_bfloat162{h0, h1};
    *(__nv_bfloat162*)&g_xh[idx + 2] = __nv_bfloat162{h2, h3};
    *(__nv_bfloat162*)&g_xl[idx]     = __nv_bfloat162{l0, l1};
    *(__nv_bfloat162*)&g_xl[idx + 2] = __nv_bfloat162{l2, l3};
    if (is_lat) {
        size_t li = (size_t)(b * NQ + ql) * ND + t * 4;
        *(__nv_bfloat162*)&g_lath[li]     = __nv_bfloat162{h0, h1};
        *(__nv_bfloat162*)&g_lath[li + 2] = __nv_bfloat162{h2, h3};
        *(__nv_bfloat162*)&g_latl[li]     = __nv_bfloat162{l0, l1};
        *(__nv_bfloat162*)&g_latl[li + 2] = __nv_bfloat162{l2, l3};
    }
}

// ============ weight transpose + hi/lo split: W[K,N] -> T{hi,lo}[N,K] ======
__global__ __launch_bounds__(256) void wsplit_kernel(
    const float* __restrict__ W, __nv_bfloat16* __restrict__ Th,
    __nv_bfloat16* __restrict__ Tl)
{
    __shared__ float t[32][33];
    int bx = blockIdx.x * 32;           // n tile
    int by = blockIdx.y * 32;           // k tile
    int tx = threadIdx.x & 31, ty = threadIdx.x >> 5;
    #pragma unroll
    for (int i = 0; i < 32; i += 8)
        t[ty + i][tx] = W[(size_t)(by + ty + i) * 1024 + bx + tx];
    __syncthreads();
    #pragma unroll
    for (int i = 0; i < 32; i += 8) {
        float v = t[tx][ty + i];        // (k=by+tx, n=bx+ty+i)
        __nv_bfloat16 h = __float2bfloat16(v);
        __nv_bfloat16 l = __float2bfloat16(v - __bfloat162float(h));
        size_t o = (size_t)(bx + ty + i) * 1024 + by + tx;
        Th[o] = h; Tl[o] = l;
    }
}

// ==================== bf16 split GEMM on mma.sync (HMMA) ===================
// C[M,1024] = alpha * (Ah+Al) @ (Bh+Bl)^T ; B given [N,K] row-major (K-major).
// BM=128, BN=128, BK=32; 8 warps (2x4); 2-stage cp.async double buffer.
#define LDT 40                        // padded row stride (halves); 80B, 16B-aligned, conflict-free
#define VHALVES (128 * LDT)           // halves per variant tile
#define STGH (4 * VHALVES)            // halves per stage (Ah,Al,Bh,Bl)
#define GEMM_SMEM (2 * STGH * 2)      // bytes = 163840? no: 2*20480*2 = 81920

__device__ __forceinline__ void cp_var(uint32_t sb, uint32_t dsth,
                                       const __nv_bfloat16* __restrict__ src,
                                       int row0, int kt, int tid)
{
    #pragma unroll
    for (int j = 0; j < 2; j++) {
        int ci = tid + j * 256;               // 0..511 16B chunks
        int row = ci >> 2, c = ci & 3;
        uint32_t so = sb + (dsth + row * LDT + c * 8) * 2;
        const __nv_bfloat16* gp = src + (size_t)(row0 + row) * 1024 + kt * 32 + c * 8;
        asm volatile("cp.async.cg.shared.global [%0], [%1], 16;" :: "r"(so), "l"(gp));
    }
}

__global__ __launch_bounds__(256)
void gemm_mma_kernel(const __nv_bfloat16* __restrict__ Ah, const __nv_bfloat16* __restrict__ Al,
                     const __nv_bfloat16* __restrict__ Bh, const __nv_bfloat16* __restrict__ Bl,
                     float* __restrict__ C, float alpha)
{
    extern __shared__ __nv_bfloat16 smn[];
    uint32_t sb = smem_u32(smn);
    int tid = threadIdx.x;
    int lid = tid & 31;
    int wid = tid >> 5;
    int warp_m = wid >> 2;              // 0..1  (64 rows each)
    int warp_n = wid & 3;               // 0..3  (32 cols each)
    int bm = blockIdx.y * 128;
    int bn = blockIdx.x * 128;

    float acc[4][4][4];
    #pragma unroll
    for (int i = 0; i < 4; i++)
        #pragma unroll
        for (int j = 0; j < 4; j++)
            #pragma unroll
            for (int k = 0; k < 4; k++) acc[i][j][k] = 0.f;

    const int NT = 32;                  // 1024 / BK32

    // prologue: stage 0
    {
        uint32_t st = 0;
        cp_var(sb, st,               Ah, bm, 0, tid);
        cp_var(sb, st + VHALVES,     Al, bm, 0, tid);
        cp_var(sb, st + 2 * VHALVES, Bh, bn, 0, tid);
        cp_var(sb, st + 3 * VHALVES, Bl, bn, 0, tid);
        asm volatile("cp.async.commit_group;" ::: "memory");
    }

    // per-lane ldmatrix base offsets (halves, relative to variant tile)
    int a_row = lid & 15, a_koff = (lid >> 4) * 8;
    int b_row = lid & 7,  b_koff = ((lid >> 3) & 1) * 8;

    for (int kt = 0; kt < NT; ++kt) {
        if (kt + 1 < NT) {
            uint32_t st = ((kt + 1) & 1) * STGH;
            cp_var(sb, st,               Ah, bm, kt + 1, tid);
            cp_var(sb, st + VHALVES,     Al, bm, kt + 1, tid);
            cp_var(sb, st + 2 * VHALVES, Bh, bn, kt + 1, tid);
            cp_var(sb, st + 3 * VHALVES, Bl, bn, kt + 1, tid);
            asm volatile("cp.async.commit_group;" ::: "memory");
            asm volatile("cp.async.wait_group 1;" ::: "memory");
        } else {
            asm volatile("cp.async.wait_group 0;" ::: "memory");
        }
        __syncthreads();

        uint32_t st = (kt & 1) * STGH;
        uint32_t Ah_b = sb + (st) * 2;
        uint32_t Al_b = sb + (st + VHALVES) * 2;
        uint32_t Bh_b = sb + (st + 2 * VHALVES) * 2;
        uint32_t Bl_b = sb + (st + 3 * VHALVES) * 2;

        #pragma unroll
        for (int ks = 0; ks < 2; ++ks) {
            uint32_t ah[4][4], al[4][4], bf[4][2];
            #pragma unroll
            for (int mt = 0; mt < 4; mt++) {
                uint32_t off = ((warp_m * 64 + mt * 16 + a_row) * LDT + ks * 16 + a_koff) * 2;
                ldm_x4(ah[mt], Ah_b + off);
            }
            #pragma unroll
            for (int nt = 0; nt < 4; nt++) {
                uint32_t off = ((warp_n * 32 + nt * 8 + b_row) * LDT + ks * 16 + b_koff) * 2;
                ldm_x2(bf[nt], Bh_b + off);
            }
            #pragma unroll
            for (int mt = 0; mt < 4; mt++)
                #pragma unroll
                for (int nt = 0; nt < 4; nt++) mma_bf16(acc[mt][nt], ah[mt], bf[nt]);
            #pragma unroll
            for (int mt = 0; mt < 4; mt++) {
                uint32_t off = ((warp_m * 64 + mt * 16 + a_row) * LDT + ks * 16 + a_koff) * 2;
                ldm_x4(al[mt], Al_b + off);
            }
            #pragma unroll
            for (int mt = 0; mt < 4; mt++)
                #pragma unroll
                for (int nt = 0; nt < 4; nt++) mma_bf16(acc[mt][nt], al[mt], bf[nt]);
            #pragma unroll
            for (int nt = 0; nt < 4; nt++) {
                uint32_t off = ((warp_n * 32 + nt * 8 + b_row) * LDT + ks * 16 + b_koff) * 2;
                ldm_x2(bf[nt], Bl_b + off);
            }
            #pragma unroll
            for (int mt = 0; mt < 4; mt++)
                #pragma unroll
                for (int nt = 0; nt < 4; nt++) mma_bf16(acc[mt][nt], ah[mt], bf[nt]);
        }
        __syncthreads();
    }

    // epilogue: c0,c1 -> (row, col..col+1); c2,c3 -> (row+8, ...)
    int r0 = bm + warp_m * 64 + (lid >> 2);
    int c0 = bn + warp_n * 32 + (lid & 3) * 2;
    #pragma unroll
    for (int mt = 0; mt < 4; mt++) {
        #pragma unroll
        for (int nt = 0; nt < 4; nt++) {
            float* p0 = C + (size_t)(r0 + mt * 16) * 1024 + c0 + nt * 8;
            float* p1 = C + (size_t)(r0 + mt * 16 + 8) * 1024 + c0 + nt * 8;
            *(float2*)p0 = make_float2(alpha * acc[mt][nt][0], alpha * acc[mt][nt][1]);
            *(float2*)p1 = make_float2(alpha * acc[mt][nt][2], alpha * acc[mt][nt][3]);
        }
    }
}

// ==================== Flash attention, split-KV=4 ==========================
#define CH 64
#define SMP 68
#define ATTN_SMEM ((4 * 64 * SMP + 3 * 64) * 4)
#define NSPLIT 4
#define CPS 17

__global__ __launch_bounds__(256) void attn_kernel()
{
    extern __shared__ float sm[];
    float* qs   = sm;
    float* ks   = qs + 64 * SMP;
    float* vs   = ks + 64 * SMP;
    float* ps   = vs + 64 * SMP;
    float* mrow = ps + 64 * SMP;
    float* lrow = mrow + 64;
    float* srow = lrow + 64;

    int tid = threadIdx.x;
    int bh = blockIdx.x;
    int b = bh >> 4, h = bh & 15;
    int sp = blockIdx.y;
    int c0 = sp * CPS;
    int c1 = min(NFL / CH, c0 + CPS);

    {
        const float* qbase = g_q + (size_t)(b * NQ) * INNER + h * DHD;
        #pragma unroll
        for (int t = 0; t < 4; t++) {
            int fi = tid + t * 256;
            int row = fi >> 4, c4 = (fi & 15) * 4;
            *(float4*)&qs[row * SMP + c4] =
                *(const float4*)(qbase + (size_t)row * INNER + c4);
        }
    }
    if (tid < 64) { mrow[tid] = -1e30f; lrow[tid] = 0.f; }

    const float* kbase = g_k + (size_t)(b * NFL) * INNER + h * DHD;
    const float* vbase = g_v + (size_t)(b * NFL) * INNER + h * DHD;

    int q0 = (tid >> 4) * 4;
    int k0 = tid & 15;
    int v0 = (tid & 15) * 4;

    float o[4][4];
    #pragma unroll
    for (int i = 0; i < 4; i++)
        #pragma unroll
        for (int j = 0; j < 4; j++) o[i][j] = 0.f;

    float4 kf[4], vf[4];
    {
        size_t off = (size_t)c0 * CH * INNER;
        #pragma unroll
        for (int t = 0; t < 4; t++) {
            int fi = tid + t * 256;
            int row = fi >> 4, c4 = (fi & 15) * 4;
            kf[t] = *(const float4*)(kbase + off + (size_t)row * INNER + c4);
            vf[t] = *(const float4*)(vbase + off + (size_t)row * INNER + c4);
        }
    }

    for (int c = c0; c < c1; ++c) {
        __syncthreads();
        #pragma unroll
        for (int t = 0; t < 4; t++) {
            int fi = tid + t * 256;
            int row = fi >> 4, c4 = (fi & 15) * 4;
            *(float4*)&ks[row * SMP + c4] = kf[t];
            *(float4*)&vs[row * SMP + c4] = vf[t];
        }
        __syncthreads();
        if (c + 1 < c1) {
            size_t off = (size_t)(c + 1) * CH * INNER;
            #pragma unroll
            for (int t = 0; t < 4; t++) {
                int fi = tid + t * 256;
                int row = fi >> 4, c4 = (fi & 15) * 4;
                kf[t] = *(const float4*)(kbase + off + (size_t)row * INNER + c4);
                vf[t] = *(const float4*)(vbase + off + (size_t)row * INNER + c4);
            }
        }
        float s[4][4];
        #pragma unroll
        for (int i = 0; i < 4; i++)
            #pragma unroll
            for (int j = 0; j < 4; j++) s[i][j] = 0.f;
        #pragma unroll
        for (int d = 0; d < 64; d += 4) {
            float4 qa[4], ka[4];
            #pragma unroll
            for (int i = 0; i < 4; i++) qa[i] = *(const float4*)&qs[(q0 + i) * SMP + d];
            #pragma unroll
            for (int j = 0; j < 4; j++) ka[j] = *(const float4*)&ks[(k0 + j * 16) * SMP + d];
            #pragma unroll
            for (int i = 0; i < 4; i++)
                #pragma unroll
                for (int j = 0; j < 4; j++)
                    s[i][j] += qa[i].x * ka[j].x + qa[i].y * ka[j].y +
                               qa[i].z * ka[j].z + qa[i].w * ka[j].w;
        }
        #pragma unroll
        for (int i = 0; i < 4; i++)
            #pragma unroll
            for (int j = 0; j < 4; j++)
                ps[(q0 + i) * SMP + k0 + j * 16] = s[i][j];
        __syncthreads();
        {
            int row = tid >> 2;
            int j0  = (tid & 3) * 16;
            float* prow = ps + row * SMP + j0;
            float pv[16];
            float cmax = -1e30f;
            #pragma unroll
            for (int j = 0; j < 16; j++) { pv[j] = prow[j]; cmax = fmaxf(cmax, pv[j]); }
            cmax = fmaxf(cmax, __shfl_xor_sync(0xffffffffu, cmax, 1));
            cmax = fmaxf(cmax, __shfl_xor_sync(0xffffffffu, cmax, 2));
            float mold = mrow[row];
            float mnew = fmaxf(mold, cmax);
            float sum = 0.f;
            #pragma unroll
            for (int j = 0; j < 16; j++) { pv[j] = __expf(pv[j] - mnew); sum += pv[j]; }
            sum += __shfl_xor_sync(0xffffffffu, sum, 1);
            sum += __shfl_xor_sync(0xffffffffu, sum, 2);
            #pragma unroll
            for (int j = 0; j < 16; j++) prow[j] = pv[j];
            if ((tid & 3) == 0) {
                float sc = __expf(mold - mnew);
                srow[row] = sc;
                lrow[row] = lrow[row] * sc + sum;
                mrow[row] = mnew;
            }
        }
        __syncthreads();
        #pragma unroll
        for (int i = 0; i < 4; i++) {
            float sc = srow[q0 + i];
            #pragma unroll
            for (int j = 0; j < 4; j++) o[i][j] *= sc;
        }
        #pragma unroll
        for (int j4 = 0; j4 < 16; ++j4) {
            float4 pa[4], va[4];
            #pragma unroll
            for (int i = 0; i < 4; i++) pa[i] = *(const float4*)&ps[(q0 + i) * SMP + j4 * 4];
            #pragma unroll
            for (int l = 0; l < 4; l++) va[l] = *(const float4*)&vs[(j4 * 4 + l) * SMP + v0];
            #pragma unroll
            for (int i = 0; i < 4; i++) {
                o[i][0] += pa[i].x * va[0].x + pa[i].y * va[1].x + pa[i].z * va[2].x + pa[i].w * va[3].x;
                o[i][1] += pa[i].x * va[0].y + pa[i].y * va[1].y + pa[i].z * va[2].y + pa[i].w * va[3].y;
                o[i][2] += pa[i].x * va[0].z + pa[i].y * va[1].z + pa[i].z * va[2].z + pa[i].w * va[3].z;
                o[i][3] += pa[i].x * va[0].w + pa[i].y * va[1].w + pa[i].z * va[2].w + pa[i].w * va[3].w;
            }
        }
    }
    __syncthreads();
    int pidx = bh * NSPLIT + sp;
    #pragma unroll
    for (int i = 0; i < 4; i++)
        *(float4*)&g_opart[((size_t)pidx * 64 + q0 + i) * 64 + v0] =
            make_float4(o[i][0], o[i][1], o[i][2], o[i][3]);
    if (tid < 64) {
        g_mpart[pidx * 64 + tid] = mrow[tid];
        g_lpart[pidx * 64 + tid] = lrow[tid];
    }
}

// ---------------- merge splits -> attn out hi/lo ---------------------------
__global__ __launch_bounds__(256) void attn_merge_kernel()
{
    int bh = blockIdx.x;
    int b = bh >> 4, h = bh & 15;
    int row = threadIdx.x >> 2;
    int cg  = threadIdx.x & 3;
    float m[NSPLIT], l[NSPLIT];
    #pragma unroll
    for (int s = 0; s < NSPLIT; s++) {
        m[s] = g_mpart[(bh * NSPLIT + s) * 64 + row];
        l[s] = g_lpart[(bh * NSPLIT + s) * 64 + row];
    }
    float M = m[0];
    #pragma unroll
    for (int s = 1; s < NSPLIT; s++) M = fmaxf(M, m[s]);
    float w[NSPLIT]; float L = 0.f;
    #pragma unroll
    for (int s = 0; s < NSPLIT; s++) { w[s] = __expf(m[s] - M); L += w[s] * l[s]; }
    float inv = 1.0f / L;
    #pragma unroll
    for (int j = 0; j < 16; j++) {
        int col = cg * 16 + j;
        float acc = 0.f;
        #pragma unroll
        for (int s = 0; s < NSPLIT; s++)
            acc += g_opart[((size_t)(bh * NSPLIT + s) * 64 + row) * 64 + col] * w[s];
        acc *= inv;
        __nv_bfloat16 hh = __float2bfloat16(acc);
        size_t oidx = (size_t)(b * NQ + row) * INNER + h * DHD + col;
        g_ah[oidx] = hh;
        g_al[oidx] = __float2bfloat16(acc - __bfloat162float(hh));
    }
}

// ==================== launcher =============================================
#define GEMM_SMEM_BYTES (2 * STGH * 2)   // 81920

extern "C" void kernel_launch(void* const* d_in, const int* in_sizes, int n_in,
                              void* d_out, int out_size)
{
    const float* features = (const float*)d_in[0];
    const float* latents  = (const float*)d_in[1];
    const float* lnm_w    = (const float*)d_in[2];
    const float* lnm_b    = (const float*)d_in[3];
    const float* lnl_w    = (const float*)d_in[4];
    const float* lnl_b    = (const float*)d_in[5];
    const float* Wq       = (const float*)d_in[6];
    const float* Wk       = (const float*)d_in[7];
    const float* Wv       = (const float*)d_in[8];
    const float* Wo       = (const float*)d_in[9];
    float* out = (float*)d_out;

    __nv_bfloat16 *p_xh, *p_xl, *p_lath, *p_latl;
    __nv_bfloat16 *p_wqh, *p_wql, *p_wkh, *p_wkl, *p_wvh, *p_wvl, *p_woh, *p_wol;
    __nv_bfloat16 *p_ah, *p_al;
    float *p_q, *p_k, *p_v;
    cudaGetSymbolAddress((void**)&p_xh, g_xh);   cudaGetSymbolAddress((void**)&p_xl, g_xl);
    cudaGetSymbolAddress((void**)&p_lath, g_lath); cudaGetSymbolAddress((void**)&p_latl, g_latl);
    cudaGetSymbolAddress((void**)&p_wqh, g_wqh); cudaGetSymbolAddress((void**)&p_wql, g_wql);
    cudaGetSymbolAddress((void**)&p_wkh, g_wkh); cudaGetSymbolAddress((void**)&p_wkl, g_wkl);
    cudaGetSymbolAddress((void**)&p_wvh, g_wvh); cudaGetSymbolAddress((void**)&p_wvl, g_wvl);
    cudaGetSymbolAddress((void**)&p_woh, g_woh); cudaGetSymbolAddress((void**)&p_wol, g_wol);
    cudaGetSymbolAddress((void**)&p_ah, g_ah);   cudaGetSymbolAddress((void**)&p_al, g_al);
    cudaGetSymbolAddress((void**)&p_q, g_q);
    cudaGetSymbolAddress((void**)&p_k, g_k);     cudaGetSymbolAddress((void**)&p_v, g_v);

    cudaFuncSetAttribute(gemm_mma_kernel,
                         cudaFuncAttributeMaxDynamicSharedMemorySize, GEMM_SMEM_BYTES);
    cudaFuncSetAttribute(attn_kernel,
                         cudaFuncAttributeMaxDynamicSharedMemorySize, ATTN_SMEM);

    // 1) LayerNorm -> bf16 hi/lo
    ln_kernel<<<NB * NFL, 256>>>(features, latents, lnm_w, lnm_b, lnl_w, lnl_b);

    // 2) weight transpose + split
    dim3 gW(32, 32);
    wsplit_kernel<<<gW, 256>>>(Wq, p_wqh, p_wql);
    wsplit_kernel<<<gW, 256>>>(Wk, p_wkh, p_wkl);
    wsplit_kernel<<<gW, 256>>>(Wv, p_wvh, p_wvl);
    wsplit_kernel<<<gW, 256>>>(Wo, p_woh, p_wol);

    // 3) K / V projections (HMMA bf16 split)
    dim3 gKV(8, MKV / 128);
    gemm_mma_kernel<<<gKV, 256, GEMM_SMEM_BYTES>>>(p_xh, p_xl, p_wkh, p_wkl, p_k, 1.0f);
    gemm_mma_kernel<<<gKV, 256, GEMM_SMEM_BYTES>>>(p_xh, p_xl, p_wvh, p_wvl, p_v, 1.0f);

    // 4) Q projection (scale folded)
    dim3 gQ(8, MQ / 128);
    gemm_mma_kernel<<<gQ, 256, GEMM_SMEM_BYTES>>>(p_lath, p_latl, p_wqh, p_wql, p_q, 0.125f);

    // 5) attention split-KV + merge
    dim3 gA(NB * NH, NSPLIT);
    attn_kernel<<<gA, 256, ATTN_SMEM>>>();
    attn_merge_kernel<<<NB * NH, 256>>>();

    // 6) output projection
    gemm_mma_kernel<<<gQ, 256, GEMM_SMEM_BYTES>>>(p_ah, p_al, p_woh, p_wol, out, 1.0f);
}

// round 7
// speedup vs baseline: 2.2309x; 1.0806x over previous
#include <cuda_runtime.h>
#include <cuda_bf16.h>
#include <math.h>
#include <stdint.h>

#define NB 8
#define NF 4096
#define NQ 64
#define ND 1024
#define NH 16
#define DHD 64
#define NFL 4160            // NF + NQ
#define INNER 1024
#define MKV (NB*NFL)        // 33280
#define MQ  (NB*NQ)         // 512

// ---------------- scratch (device globals; no allocation allowed) ----------
__device__ __nv_bfloat16 g_xh[34078720];    // LN([feat;lat]) hi  (B,FL,D)
__device__ __nv_bfloat16 g_xl[34078720];    // LN([feat;lat]) lo
__device__ __nv_bfloat16 g_lath[524288];    // LN(latents) hi, contiguous (B,Q,D)
__device__ __nv_bfloat16 g_latl[524288];
__device__ __nv_bfloat16 g_wqh[1048576], g_wql[1048576];   // W^T hi/lo  [N,K]
__device__ __nv_bfloat16 g_wkh[1048576], g_wkl[1048576];
__device__ __nv_bfloat16 g_wvh[1048576], g_wvl[1048576];
__device__ __nv_bfloat16 g_woh[1048576], g_wol[1048576];
__device__ __nv_bfloat16 g_qh[524288], g_ql[524288];        // q proj hi/lo (scaled 1/8)
__device__ __nv_bfloat16 g_kh[34078720], g_kl[34078720];    // k proj hi/lo
__device__ __nv_bfloat16 g_vh[34078720], g_vl[34078720];    // v proj hi/lo
__device__ float g_opart[2097152];          // 128 bh * 4 splits * 64 * 64
__device__ float g_mpart[32768];
__device__ float g_lpart[32768];
__device__ __nv_bfloat16 g_ah[524288];      // attn out hi/lo (B,Q,inner)
__device__ __nv_bfloat16 g_al[524288];

// ==================== helpers ==============================================
__device__ __forceinline__ uint32_t smem_u32(const void* p) {
    uint32_t a;
    asm("{ .reg .u64 t; cvta.to.shared.u64 t, %1; cvt.u32.u64 %0, t; }" : "=r"(a) : "l"(p));
    return a;
}
__device__ __forceinline__ void ldm_x4(uint32_t* r, uint32_t addr) {
    asm volatile("ldmatrix.sync.aligned.m8n8.x4.shared.b16 {%0,%1,%2,%3}, [%4];"
                 : "=r"(r[0]), "=r"(r[1]), "=r"(r[2]), "=r"(r[3]) : "r"(addr));
}
__device__ __forceinline__ void ldm_x2(uint32_t* r, uint32_t addr) {
    asm volatile("ldmatrix.sync.aligned.m8n8.x2.shared.b16 {%0,%1}, [%2];"
                 : "=r"(r[0]), "=r"(r[1]) : "r"(addr));
}
__device__ __forceinline__ void ldm_x2_t(uint32_t* r, uint32_t addr) {
    asm volatile("ldmatrix.sync.aligned.m8n8.x2.trans.shared.b16 {%0,%1}, [%2];"
                 : "=r"(r[0]), "=r"(r[1]) : "r"(addr));
}
__device__ __forceinline__ void mma_bf16(float* c, const uint32_t* a, const uint32_t* b) {
    asm volatile("mma.sync.aligned.m16n8k16.row.col.f32.bf16.bf16.f32 "
                 "{%0,%1,%2,%3}, {%4,%5,%6,%7}, {%8,%9}, {%0,%1,%2,%3};"
                 : "+f"(c[0]), "+f"(c[1]), "+f"(c[2]), "+f"(c[3])
                 : "r"(a[0]), "r"(a[1]), "r"(a[2]), "r"(a[3]), "r"(b[0]), "r"(b[1]));
}
// pack: low half = lo, high half = hi
__device__ __forceinline__ uint32_t packbf(float lo, float hi) {
    uint32_t r;
    asm("cvt.rn.bf16x2.f32 %0, %1, %2;" : "=r"(r) : "f"(hi), "f"(lo));
    return r;
}

// ==================== LayerNorm -> bf16 hi/lo ==============================
__global__ __launch_bounds__(256) void ln_kernel(
    const float* __restrict__ feat, const float* __restrict__ lat,
    const float* __restrict__ lnm_w, const float* __restrict__ lnm_b,
    const float* __restrict__ lnl_w, const float* __restrict__ lnl_b)
{
    int r = blockIdx.x;
    int b = r / NFL, f = r - b * NFL;
    const float* src; const float* w; const float* bias;
    bool is_lat = (f >= NF);
    int ql = 0;
    if (!is_lat) { src = feat + (size_t)(b * NF + f) * ND; w = lnm_w; bias = lnm_b; }
    else { ql = f - NF; src = lat + (size_t)(b * NQ + ql) * ND; w = lnl_w; bias = lnl_b; }

    int t = threadIdx.x;
    float4 v = ((const float4*)src)[t];
    float s  = v.x + v.y + v.z + v.w;
    float ss = v.x*v.x + v.y*v.y + v.z*v.z + v.w*v.w;

    __shared__ float red[2][8];
    __shared__ float stat[2];
    #pragma unroll
    for (int o = 16; o > 0; o >>= 1) {
        s  += __shfl_down_sync(0xffffffffu, s,  o);
        ss += __shfl_down_sync(0xffffffffu, ss, o);
    }
    int wid = t >> 5, lid = t & 31;
    if (lid == 0) { red[0][wid] = s; red[1][wid] = ss; }
    __syncthreads();
    if (t == 0) {
        float a = 0.f, c = 0.f;
        #pragma unroll
        for (int i = 0; i < 8; i++) { a += red[0][i]; c += red[1][i]; }
        float mu  = a * (1.0f / ND);
        float var = c * (1.0f / ND) - mu * mu;
        stat[0] = mu; stat[1] = rsqrtf(var + 1e-5f);
    }
    __syncthreads();
    float mu = stat[0], inv = stat[1];
    float4 w4 = ((const float4*)w)[t];
    float4 b4 = ((const float4*)bias)[t];
    float o0 = (v.x - mu) * inv * w4.x + b4.x;
    float o1 = (v.y - mu) * inv * w4.y + b4.y;
    float o2 = (v.z - mu) * inv * w4.z + b4.z;
    float o3 = (v.w - mu) * inv * w4.w + b4.w;

    __nv_bfloat16 h0 = __float2bfloat16(o0), h1 = __float2bfloat16(o1);
    __nv_bfloat16 h2 = __float2bfloat16(o2), h3 = __float2bfloat16(o3);
    __nv_bfloat16 l0 = __float2bfloat16(o0 - __bfloat162float(h0));
    __nv_bfloat16 l1 = __float2bfloat16(o1 - __bfloat162float(h1));
    __nv_bfloat16 l2 = __float2bfloat16(o2 - __bfloat162float(h2));
    __nv_bfloat16 l3 = __float2bfloat16(o3 - __bfloat162float(h3));

    size_t idx = (size_t)r * ND + t * 4;
    *(__nv_bfloat162*)&g_xh[idx]     = __nv_bfloat162{h0, h1};
    *(__nv_bfloat162*)&g_xh[idx + 2] = __nv_bfloat162{h2, h3};
    *(__nv_bfloat162*)&g_xl[idx]     = __nv_bfloat162{l0, l1};
    *(__nv_bfloat162*)&g_xl[idx + 2] = __nv_bfloat162{l2, l3};
    if (is_lat) {
        size_t li = (size_t)(b * NQ + ql) * ND + t * 4;
        *(__nv_bfloat162*)&g_lath[li]     = __nv_bfloat162{h0, h1};
        *(__nv_bfloat162*)&g_lath[li + 2] = __nv_bfloat162{h2, h3};
        *(__nv_bfloat162*)&g_latl[li]     = __nv_bfloat162{l0, l1};
        *(__nv_bfloat162*)&g_latl[li + 2] = __nv_bfloat162{l2, l3};
    }
}

// ============ weight transpose + hi/lo split: W[K,N] -> T{hi,lo}[N,K] ======
__global__ __launch_bounds__(256) void wsplit_kernel(
    const float* __restrict__ W, __nv_bfloat16* __restrict__ Th,
    __nv_bfloat16* __restrict__ Tl)
{
    __shared__ float t[32][33];
    int bx = blockIdx.x * 32;
    int by = blockIdx.y * 32;
    int tx = threadIdx.x & 31, ty = threadIdx.x >> 5;
    #pragma unroll
    for (int i = 0; i < 32; i += 8)
        t[ty + i][tx] = W[(size_t)(by + ty + i) * 1024 + bx + tx];
    __syncthreads();
    #pragma unroll
    for (int i = 0; i < 32; i += 8) {
        float v = t[tx][ty + i];
        __nv_bfloat16 h = __float2bfloat16(v);
        __nv_bfloat16 l = __float2bfloat16(v - __bfloat162float(h));
        size_t o = (size_t)(bx + ty + i) * 1024 + by + tx;
        Th[o] = h; Tl[o] = l;
    }
}

// ==================== bf16 split GEMM on mma.sync (HMMA) ===================
#define LDT 40
#define VHALVES (128 * LDT)
#define STGH (4 * VHALVES)
#define GEMM_SMEM_BYTES (2 * STGH * 2)   // 81920

__device__ __forceinline__ void cp_var(uint32_t sb, uint32_t dsth,
                                       const __nv_bfloat16* __restrict__ src,
                                       int row0, int kt, int tid)
{
    #pragma unroll
    for (int j = 0; j < 2; j++) {
        int ci = tid + j * 256;
        int row = ci >> 2, c = ci & 3;
        uint32_t so = sb + (dsth + row * LDT + c * 8) * 2;
        const __nv_bfloat16* gp = src + (size_t)(row0 + row) * 1024 + kt * 32 + c * 8;
        asm volatile("cp.async.cg.shared.global [%0], [%1], 16;" :: "r"(so), "l"(gp));
    }
}

__global__ __launch_bounds__(256)
void gemm_mma_kernel(const __nv_bfloat16* __restrict__ Ah, const __nv_bfloat16* __restrict__ Al,
                     const __nv_bfloat16* __restrict__ Bh, const __nv_bfloat16* __restrict__ Bl,
                     float* __restrict__ Cf, __nv_bfloat16* __restrict__ Ch,
                     __nv_bfloat16* __restrict__ Cl, float alpha)
{
    extern __shared__ __nv_bfloat16 smn[];
    uint32_t sb = smem_u32(smn);
    int tid = threadIdx.x;
    int lid = tid & 31;
    int wid = tid >> 5;
    int warp_m = wid >> 2;
    int warp_n = wid & 3;
    int bm = blockIdx.y * 128;
    int bn = blockIdx.x * 128;

    float acc[4][4][4];
    #pragma unroll
    for (int i = 0; i < 4; i++)
        #pragma unroll
        for (int j = 0; j < 4; j++)
            #pragma unroll
            for (int k = 0; k < 4; k++) acc[i][j][k] = 0.f;

    const int NT = 32;
    {
        uint32_t st = 0;
        cp_var(sb, st,               Ah, bm, 0, tid);
        cp_var(sb, st + VHALVES,     Al, bm, 0, tid);
        cp_var(sb, st + 2 * VHALVES, Bh, bn, 0, tid);
        cp_var(sb, st + 3 * VHALVES, Bl, bn, 0, tid);
        asm volatile("cp.async.commit_group;" ::: "memory");
    }
    int a_row = lid & 15, a_koff = (lid >> 4) * 8;
    int b_row = lid & 7,  b_koff = ((lid >> 3) & 1) * 8;

    for (int kt = 0; kt < NT; ++kt) {
        if (kt + 1 < NT) {
            uint32_t st = ((kt + 1) & 1) * STGH;
            cp_var(sb, st,               Ah, bm, kt + 1, tid);
            cp_var(sb, st + VHALVES,     Al, bm, kt + 1, tid);
            cp_var(sb, st + 2 * VHALVES, Bh, bn, kt + 1, tid);
            cp_var(sb, st + 3 * VHALVES, Bl, bn, kt + 1, tid);
            asm volatile("cp.async.commit_group;" ::: "memory");
            asm volatile("cp.async.wait_group 1;" ::: "memory");
        } else {
            asm volatile("cp.async.wait_group 0;" ::: "memory");
        }
        __syncthreads();

        uint32_t st = (kt & 1) * STGH;
        uint32_t Ah_b = sb + (st) * 2;
        uint32_t Al_b = sb + (st + VHALVES) * 2;
        uint32_t Bh_b = sb + (st + 2 * VHALVES) * 2;
        uint32_t Bl_b = sb + (st + 3 * VHALVES) * 2;

        #pragma unroll
        for (int ks = 0; ks < 2; ++ks) {
            uint32_t ah[4][4], al[4][4], bf[4][2];
            #pragma unroll
            for (int mt = 0; mt < 4; mt++) {
                uint32_t off = ((warp_m * 64 + mt * 16 + a_row) * LDT + ks * 16 + a_koff) * 2;
                ldm_x4(ah[mt], Ah_b + off);
            }
            #pragma unroll
            for (int nt = 0; nt < 4; nt++) {
                uint32_t off = ((warp_n * 32 + nt * 8 + b_row) * LDT + ks * 16 + b_koff) * 2;
                ldm_x2(bf[nt], Bh_b + off);
            }
            #pragma unroll
            for (int mt = 0; mt < 4; mt++)
                #pragma unroll
                for (int nt = 0; nt < 4; nt++) mma_bf16(acc[mt][nt], ah[mt], bf[nt]);
            #pragma unroll
            for (int mt = 0; mt < 4; mt++) {
                uint32_t off = ((warp_m * 64 + mt * 16 + a_row) * LDT + ks * 16 + a_koff) * 2;
                ldm_x4(al[mt], Al_b + off);
            }
            #pragma unroll
            for (int mt = 0; mt < 4; mt++)
                #pragma unroll
                for (int nt = 0; nt < 4; nt++) mma_bf16(acc[mt][nt], al[mt], bf[nt]);
            #pragma unroll
            for (int nt = 0; nt < 4; nt++) {
                uint32_t off = ((warp_n * 32 + nt * 8 + b_row) * LDT + ks * 16 + b_koff) * 2;
                ldm_x2(bf[nt], Bl_b + off);
            }
            #pragma unroll
            for (int mt = 0; mt < 4; mt++)
                #pragma unroll
                for (int nt = 0; nt < 4; nt++) mma_bf16(acc[mt][nt], ah[mt], bf[nt]);
        }
        __syncthreads();
    }

    int r0 = bm + warp_m * 64 + (lid >> 2);
    int c0 = bn + warp_n * 32 + (lid & 3) * 2;
    if (Cf) {
        #pragma unroll
        for (int mt = 0; mt < 4; mt++) {
            #pragma unroll
            for (int nt = 0; nt < 4; nt++) {
                float* p0 = Cf + (size_t)(r0 + mt * 16) * 1024 + c0 + nt * 8;
                float* p1 = Cf + (size_t)(r0 + mt * 16 + 8) * 1024 + c0 + nt * 8;
                *(float2*)p0 = make_float2(alpha * acc[mt][nt][0], alpha * acc[mt][nt][1]);
                *(float2*)p1 = make_float2(alpha * acc[mt][nt][2], alpha * acc[mt][nt][3]);
            }
        }
    } else {
        #pragma unroll
        for (int mt = 0; mt < 4; mt++) {
            #pragma unroll
            for (int nt = 0; nt < 4; nt++) {
                #pragma unroll
                for (int half = 0; half < 2; half++) {
                    float v0 = alpha * acc[mt][nt][half * 2];
                    float v1 = alpha * acc[mt][nt][half * 2 + 1];
                    __nv_bfloat16 h0 = __float2bfloat16(v0), h1 = __float2bfloat16(v1);
                    __nv_bfloat16 l0 = __float2bfloat16(v0 - __bfloat162float(h0));
                    __nv_bfloat16 l1 = __float2bfloat16(v1 - __bfloat162float(h1));
                    size_t o = (size_t)(r0 + mt * 16 + half * 8) * 1024 + c0 + nt * 8;
                    *(__nv_bfloat162*)&Ch[o] = __nv_bfloat162{h0, h1};
                    *(__nv_bfloat162*)&Cl[o] = __nv_bfloat162{l0, l1};
                }
            }
        }
    }
}

// ==================== tensor-core flash attention, split-KV=4 ==============
#define NSPLIT 4
#define CPS 17
#define ASTR 72                       // padded row stride (halves)
#define QTILE (64 * ASTR)             // 4608 halves per tile variant
#define ATTN_SMEM ((2 * QTILE + 2 * 4 * QTILE) * 2)   // 92160 bytes

__device__ __forceinline__ void stage_kv(uint32_t sb, uint32_t stbase,
    const __nv_bfloat16* kh, const __nv_bfloat16* kl,
    const __nv_bfloat16* vh, const __nv_bfloat16* vl, size_t off, int tid)
{
    const __nv_bfloat16* srcs[4] = {kh, kl, vh, vl};
    #pragma unroll
    for (int j = 0; j < 16; j++) {
        int ci = tid + j * 128;               // 0..2047
        int tile = ci >> 9, row = (ci >> 3) & 63, c = ci & 7;
        uint32_t dst = sb + (stbase + tile * QTILE + row * ASTR) * 2 + c * 16;
        const __nv_bfloat16* src = srcs[tile] + off + (size_t)row * INNER + c * 8;
        asm volatile("cp.async.cg.shared.global [%0], [%1], 16;" :: "r"(dst), "l"(src));
    }
}

__global__ __launch_bounds__(128) void attn_kernel()
{
    extern __shared__ __nv_bfloat16 asmem[];
    uint32_t sb = smem_u32(asmem);
    const uint32_t QH = 0, QL = QTILE, ST0 = 2 * QTILE;

    int tid = threadIdx.x, lid = tid & 31, wid = tid >> 5;
    int bh = blockIdx.x, b = bh >> 4, h = bh & 15;
    int sp = blockIdx.y;
    int c0 = sp * CPS, c1 = min(65, c0 + CPS);

    const __nv_bfloat16* qhg = g_qh + (size_t)(b * NQ) * INNER + h * DHD;
    const __nv_bfloat16* qlg = g_ql + (size_t)(b * NQ) * INNER + h * DHD;
    const __nv_bfloat16* khg = g_kh + (size_t)(b * NFL) * INNER + h * DHD;
    const __nv_bfloat16* klg = g_kl + (size_t)(b * NFL) * INNER + h * DHD;
    const __nv_bfloat16* vhg = g_vh + (size_t)(b * NFL) * INNER + h * DHD;
    const __nv_bfloat16* vlg = g_vl + (size_t)(b * NFL) * INNER + h * DHD;

    // stage Q (both variants) + chunk c0, one commit group
    #pragma unroll
    for (int j = 0; j < 8; j++) {
        int ci = tid + j * 128;               // 0..1023
        int tile = ci >> 9, row = (ci >> 3) & 63, c = ci & 7;
        uint32_t dst = sb + ((tile ? QL : QH) + row * ASTR) * 2 + c * 16;
        const __nv_bfloat16* src = (tile ? qlg : qhg) + (size_t)row * INNER + c * 8;
        asm volatile("cp.async.cg.shared.global [%0], [%1], 16;" :: "r"(dst), "l"(src));
    }
    stage_kv(sb, ST0, khg, klg, vhg, vlg, (size_t)c0 * 64 * INNER, tid);
    asm volatile("cp.async.commit_group;" ::: "memory");

    float oc[8][4];
    #pragma unroll
    for (int i = 0; i < 8; i++)
        #pragma unroll
        for (int j = 0; j < 4; j++) oc[i][j] = 0.f;
    float m0 = -1e30f, m1 = -1e30f, l0 = 0.f, l1 = 0.f;

    uint32_t qhf[4][4], qlf[4][4];
    bool qloaded = false;

    for (int c = c0; c < c1; ++c) {
        int p = (c - c0) & 1;
        if (c + 1 < c1) {
            stage_kv(sb, ST0 + (1 - p) * 4 * QTILE, khg, klg, vhg, vlg,
                     (size_t)(c + 1) * 64 * INNER, tid);
            asm volatile("cp.async.commit_group;" ::: "memory");
            asm volatile("cp.async.wait_group 1;" ::: "memory");
        } else {
            asm volatile("cp.async.wait_group 0;" ::: "memory");
        }
        __syncthreads();

        if (!qloaded) {
            #pragma unroll
            for (int t = 0; t < 4; t++) {
                uint32_t ao = ((wid * 16 + (lid & 15)) * ASTR + t * 16 + (lid >> 4) * 8) * 2;
                ldm_x4(qhf[t], sb + QH * 2 + ao);
                ldm_x4(qlf[t], sb + QL * 2 + ao);
            }
            qloaded = true;
        }
        uint32_t stb = ST0 + p * 4 * QTILE;     // kh tile base (halves)

        // ---- S = Q K^T (3-term) ----
        float sc[8][4];
        #pragma unroll
        for (int j = 0; j < 8; j++)
            #pragma unroll
            for (int k = 0; k < 4; k++) sc[j][k] = 0.f;
        #pragma unroll
        for (int t = 0; t < 4; t++) {
            #pragma unroll
            for (int j = 0; j < 8; j++) {
                uint32_t ko = ((8 * j + (lid & 7)) * ASTR + t * 16 + ((lid >> 3) & 1) * 8) * 2;
                uint32_t bK[2], bKl[2];
                ldm_x2(bK,  sb + stb * 2 + ko);
                ldm_x2(bKl, sb + (stb + QTILE) * 2 + ko);
                mma_bf16(sc[j], qhf[t], bK);
                mma_bf16(sc[j], qlf[t], bK);
                mma_bf16(sc[j], qhf[t], bKl);
            }
        }
        // ---- online softmax (rows r0=lid>>2, r1=r0+8 within warp's 16) ----
        float cm0 = -1e30f, cm1 = -1e30f;
        #pragma unroll
        for (int j = 0; j < 8; j++) {
            cm0 = fmaxf(cm0, fmaxf(sc[j][0], sc[j][1]));
            cm1 = fmaxf(cm1, fmaxf(sc[j][2], sc[j][3]));
        }
        cm0 = fmaxf(cm0, __shfl_xor_sync(0xffffffffu, cm0, 1));
        cm0 = fmaxf(cm0, __shfl_xor_sync(0xffffffffu, cm0, 2));
        cm1 = fmaxf(cm1, __shfl_xor_sync(0xffffffffu, cm1, 1));
        cm1 = fmaxf(cm1, __shfl_xor_sync(0xffffffffu, cm1, 2));
        float nm0 = fmaxf(m0, cm0), nm1 = fmaxf(m1, cm1);
        float sum0 = 0.f, sum1 = 0.f;
        #pragma unroll
        for (int j = 0; j < 8; j++) {
            sc[j][0] = __expf(sc[j][0] - nm0);
            sc[j][1] = __expf(sc[j][1] - nm0);
            sc[j][2] = __expf(sc[j][2] - nm1);
            sc[j][3] = __expf(sc[j][3] - nm1);
            sum0 += sc[j][0] + sc[j][1];
            sum1 += sc[j][2] + sc[j][3];
        }
        sum0 += __shfl_xor_sync(0xffffffffu, sum0, 1);
        sum0 += __shfl_xor_sync(0xffffffffu, sum0, 2);
        sum1 += __shfl_xor_sync(0xffffffffu, sum1, 1);
        sum1 += __shfl_xor_sync(0xffffffffu, sum1, 2);
        float e0 = __expf(m0 - nm0), e1 = __expf(m1 - nm1);
        l0 = l0 * e0 + sum0; l1 = l1 * e1 + sum1;
        m0 = nm0; m1 = nm1;
        #pragma unroll
        for (int nd = 0; nd < 8; nd++) {
            oc[nd][0] *= e0; oc[nd][1] *= e0;
            oc[nd][2] *= e1; oc[nd][3] *= e1;
        }
        // ---- pack P hi/lo A-fragments, P@V (3-term) ----
        uint32_t vstb = stb + 2 * QTILE;        // vh tile base
        #pragma unroll
        for (int t2 = 0; t2 < 4; t2++) {
            float ph[8], pl[8];
            #pragma unroll
            for (int u = 0; u < 2; u++) {       // tiles 2t2+u
                #pragma unroll
                for (int k = 0; k < 4; k++) {
                    float v = sc[2 * t2 + u][k];
                    __nv_bfloat16 hb = __float2bfloat16(v);
                    float hf = __bfloat162float(hb);
                    ph[u * 4 + k] = hf;
                    pl[u * 4 + k] = v - hf;
                }
            }
            uint32_t aph[4], apl[4];
            aph[0] = packbf(ph[0], ph[1]); aph[1] = packbf(ph[2], ph[3]);
            aph[2] = packbf(ph[4], ph[5]); aph[3] = packbf(ph[6], ph[7]);
            apl[0] = packbf(pl[0], pl[1]); apl[1] = packbf(pl[2], pl[3]);
            apl[2] = packbf(pl[4], pl[5]); apl[3] = packbf(pl[6], pl[7]);
            #pragma unroll
            for (int nd = 0; nd < 8; nd++) {
                uint32_t vo = ((16 * t2 + (lid & 15)) * ASTR + nd * 8) * 2;
                uint32_t bV[2], bVl[2];
                ldm_x2_t(bV,  sb + vstb * 2 + vo);
                ldm_x2_t(bVl, sb + (vstb + QTILE) * 2 + vo);
                mma_bf16(oc[nd], aph, bV);
                mma_bf16(oc[nd], apl, bV);
                mma_bf16(oc[nd], aph, bVl);
            }
        }
        __syncthreads();
    }
    // ---- finalize ----
    float i0 = 1.0f / l0, i1 = 1.0f / l1;
    int pidx = bh * NSPLIT + sp;
    int r0 = wid * 16 + (lid >> 2), r1 = r0 + 8;
    #pragma unroll
    for (int nd = 0; nd < 8; nd++) {
        int col = 8 * nd + (lid & 3) * 2;
        *(float2*)&g_opart[((size_t)pidx * 64 + r0) * 64 + col] =
            make_float2(oc[nd][0] * i0, oc[nd][1] * i0);
        *(float2*)&g_opart[((size_t)pidx * 64 + r1) * 64 + col] =
            make_float2(oc[nd][2] * i1, oc[nd][3] * i1);
    }
    if ((lid & 3) == 0) {
        g_mpart[pidx * 64 + r0] = m0; g_lpart[pidx * 64 + r0] = l0;
        g_mpart[pidx * 64 + r1] = m1; g_lpart[pidx * 64 + r1] = l1;
    }
}

// ---------------- merge splits -> attn out hi/lo ---------------------------
__global__ __launch_bounds__(256) void attn_merge_kernel()
{
    int bh = blockIdx.x;
    int b = bh >> 4, h = bh & 15;
    int row = threadIdx.x >> 2;
    int cg  = threadIdx.x & 3;
    float m[NSPLIT], l[NSPLIT];
    #pragma unroll
    for (int s = 0; s < NSPLIT; s++) {
        m[s] = g_mpart[(bh * NSPLIT + s) * 64 + row];
        l[s] = g_lpart[(bh * NSPLIT + s) * 64 + row];
    }
    float M = m[0];
    #pragma unroll
    for (int s = 1; s < NSPLIT; s++) M = fmaxf(M, m[s]);
    float w[NSPLIT]; float L = 0.f;
    #pragma unroll
    for (int s = 0; s < NSPLIT; s++) { w[s] = __expf(m[s] - M); L += w[s] * l[s]; }
    float inv = 1.0f / L;
    #pragma unroll
    for (int j = 0; j < 16; j++) {
        int col = cg * 16 + j;
        float acc = 0.f;
        #pragma unroll
        for (int s = 0; s < NSPLIT; s++)
            acc += g_opart[((size_t)(bh * NSPLIT + s) * 64 + row) * 64 + col] * w[s] * l[s];
        // NOTE: g_opart already divided by per-split l; multiply back: acc_s = (O_s/l_s)*w_s*l_s
        acc *= inv;
        __nv_bfloat16 hh = __float2bfloat16(acc);
        size_t oidx = (size_t)(b * NQ + row) * INNER + h * DHD + col;
        g_ah[oidx] = hh;
        g_al[oidx] = __float2bfloat16(acc - __bfloat162float(hh));
    }
}

// ==================== launcher =============================================
extern "C" void kernel_launch(void* const* d_in, const int* in_sizes, int n_in,
                              void* d_out, int out_size)
{
    const float* features = (const float*)d_in[0];
    const float* latents  = (const float*)d_in[1];
    const float* lnm_w    = (const float*)d_in[2];
    const float* lnm_b    = (const float*)d_in[3];
    const float* lnl_w    = (const float*)d_in[4];
    const float* lnl_b    = (const float*)d_in[5];
    const float* Wq       = (const float*)d_in[6];
    const float* Wk       = (const float*)d_in[7];
    const float* Wv       = (const float*)d_in[8];
    const float* Wo       = (const float*)d_in[9];
    float* out = (float*)d_out;

    __nv_bfloat16 *p_xh, *p_xl, *p_lath, *p_latl;
    __nv_bfloat16 *p_wqh, *p_wql, *p_wkh, *p_wkl, *p_wvh, *p_wvl, *p_woh, *p_wol;
    __nv_bfloat16 *p_ah, *p_al, *p_qh, *p_ql, *p_kh, *p_kl, *p_vh, *p_vl;
    cudaGetSymbolAddress((void**)&p_xh, g_xh);   cudaGetSymbolAddress((void**)&p_xl, g_xl);
    cudaGetSymbolAddress((void**)&p_lath, g_lath); cudaGetSymbolAddress((void**)&p_latl, g_latl);
    cudaGetSymbolAddress((void**)&p_wqh, g_wqh); cudaGetSymbolAddress((void**)&p_wql, g_wql);
    cudaGetSymbolAddress((void**)&p_wkh, g_wkh); cudaGetSymbolAddress((void**)&p_wkl, g_wkl);
    cudaGetSymbolAddress((void**)&p_wvh, g_wvh); cudaGetSymbolAddress((void**)&p_wvl, g_wvl);
    cudaGetSymbolAddress((void**)&p_woh, g_woh); cudaGetSymbolAddress((void**)&p_wol, g_wol);
    cudaGetSymbolAddress((void**)&p_ah, g_ah);   cudaGetSymbolAddress((void**)&p_al, g_al);
    cudaGetSymbolAddress((void**)&p_qh, g_qh);   cudaGetSymbolAddress((void**)&p_ql, g_ql);
    cudaGetSymbolAddress((void**)&p_kh, g_kh);   cudaGetSymbolAddress((void**)&p_kl, g_kl);
    cudaGetSymbolAddress((void**)&p_vh, g_vh);   cudaGetSymbolAddress((void**)&p_vl, g_vl);

    cudaFuncSetAttribute(gemm_mma_kernel,
                         cudaFuncAttributeMaxDynamicSharedMemorySize, GEMM_SMEM_BYTES);
    cudaFuncSetAttribute(attn_kernel,
                         cudaFuncAttributeMaxDynamicSharedMemorySize, ATTN_SMEM);

    // 1) LayerNorm -> bf16 hi/lo
    ln_kernel<<<NB * NFL, 256>>>(features, latents, lnm_w, lnm_b, lnl_w, lnl_b);

    // 2) weight transpose + split
    dim3 gW(32, 32);
    wsplit_kernel<<<gW, 256>>>(Wq, p_wqh, p_wql);
    wsplit_kernel<<<gW, 256>>>(Wk, p_wkh, p_wkl);
    wsplit_kernel<<<gW, 256>>>(Wv, p_wvh, p_wvl);
    wsplit_kernel<<<gW, 256>>>(Wo, p_woh, p_wol);

    // 3) K / V projections -> bf16 hi/lo
    dim3 gKV(8, MKV / 128);
    gemm_mma_kernel<<<gKV, 256, GEMM_SMEM_BYTES>>>(p_xh, p_xl, p_wkh, p_wkl,
                                                   nullptr, p_kh, p_kl, 1.0f);
    gemm_mma_kernel<<<gKV, 256, GEMM_SMEM_BYTES>>>(p_xh, p_xl, p_wvh, p_wvl,
                                                   nullptr, p_vh, p_vl, 1.0f);

    // 4) Q projection -> bf16 hi/lo (scale folded)
    dim3 gQ(8, MQ / 128);
    gemm_mma_kernel<<<gQ, 256, GEMM_SMEM_BYTES>>>(p_lath, p_latl, p_wqh, p_wql,
                                                  nullptr, p_qh, p_ql, 0.125f);

    // 5) tensor-core attention split-KV + merge
    dim3 gA(NB * NH, NSPLIT);
    attn_kernel<<<gA, 128, ATTN_SMEM>>>();
    attn_merge_kernel<<<NB * NH, 256>>>();

    // 6) output projection -> fp32 out
    gemm_mma_kernel<<<gQ, 256, GEMM_SMEM_BYTES>>>(p_ah, p_al, p_woh, p_wol,
                                                  out, nullptr, nullptr, 1.0f);
}

// round 8
// speedup vs baseline: 2.4679x; 1.1062x over previous
#include <cuda_runtime.h>
#include <cuda_bf16.h>
#include <math.h>
#include <stdint.h>

#define NB 8
#define NF 4096
#define NQ 64
#define ND 1024
#define NH 16
#define DHD 64
#define NFL 4160            // NF + NQ
#define INNER 1024
#define MKV (NB*NFL)        // 33280
#define MQ  (NB*NQ)         // 512

// ---------------- scratch (device globals; no allocation allowed) ----------
__device__ __nv_bfloat16 g_xh[34078720];    // LN([feat;lat]) hi  (B,FL,D)
__device__ __nv_bfloat16 g_xl[34078720];    // LN([feat;lat]) lo
__device__ __nv_bfloat16 g_lath[524288];    // LN(latents) hi, contiguous (B,Q,D)
__device__ __nv_bfloat16 g_latl[524288];
__device__ __nv_bfloat16 g_wqh[1048576], g_wql[1048576];   // W^T hi/lo  [N,K]
__device__ __nv_bfloat16 g_wkh[1048576], g_wkl[1048576];
__device__ __nv_bfloat16 g_wvh[1048576], g_wvl[1048576];
__device__ __nv_bfloat16 g_woh[1048576], g_wol[1048576];
__device__ __nv_bfloat16 g_qh[524288], g_ql[524288];        // q proj hi/lo (scaled 1/8)
__device__ __nv_bfloat16 g_kh[34078720], g_kl[34078720];    // k proj hi/lo
__device__ __nv_bfloat16 g_vh[34078720], g_vl[34078720];    // v proj hi/lo
__device__ float g_opart[2097152];          // 128 bh * 4 splits * 64 * 64
__device__ float g_mpart[32768];
__device__ float g_lpart[32768];
__device__ __nv_bfloat16 g_ah[524288];      // attn out hi/lo (B,Q,inner)
__device__ __nv_bfloat16 g_al[524288];

// ==================== helpers ==============================================
__device__ __forceinline__ uint32_t smem_u32(const void* p) {
    uint32_t a;
    asm("{ .reg .u64 t; cvta.to.shared.u64 t, %1; cvt.u32.u64 %0, t; }" : "=r"(a) : "l"(p));
    return a;
}
__device__ __forceinline__ void ldm_x4(uint32_t* r, uint32_t addr) {
    asm volatile("ldmatrix.sync.aligned.m8n8.x4.shared.b16 {%0,%1,%2,%3}, [%4];"
                 : "=r"(r[0]), "=r"(r[1]), "=r"(r[2]), "=r"(r[3]) : "r"(addr));
}
__device__ __forceinline__ void ldm_x2(uint32_t* r, uint32_t addr) {
    asm volatile("ldmatrix.sync.aligned.m8n8.x2.shared.b16 {%0,%1}, [%2];"
                 : "=r"(r[0]), "=r"(r[1]) : "r"(addr));
}
__device__ __forceinline__ void ldm_x2_t(uint32_t* r, uint32_t addr) {
    asm volatile("ldmatrix.sync.aligned.m8n8.x2.trans.shared.b16 {%0,%1}, [%2];"
                 : "=r"(r[0]), "=r"(r[1]) : "r"(addr));
}
__device__ __forceinline__ void mma_bf16(float* c, const uint32_t* a, const uint32_t* b) {
    asm volatile("mma.sync.aligned.m16n8k16.row.col.f32.bf16.bf16.f32 "
                 "{%0,%1,%2,%3}, {%4,%5,%6,%7}, {%8,%9}, {%0,%1,%2,%3};"
                 : "+f"(c[0]), "+f"(c[1]), "+f"(c[2]), "+f"(c[3])
                 : "r"(a[0]), "r"(a[1]), "r"(a[2]), "r"(a[3]), "r"(b[0]), "r"(b[1]));
}
// pack: low half = lo, high half = hi
__device__ __forceinline__ uint32_t packbf(float lo, float hi) {
    uint32_t r;
    asm("cvt.rn.bf16x2.f32 %0, %1, %2;" : "=r"(r) : "f"(hi), "f"(lo));
    return r;
}

// ==================== LayerNorm -> bf16 hi/lo ==============================
__global__ __launch_bounds__(256) void ln_kernel(
    const float* __restrict__ feat, const float* __restrict__ lat,
    const float* __restrict__ lnm_w, const float* __restrict__ lnm_b,
    const float* __restrict__ lnl_w, const float* __restrict__ lnl_b)
{
    int r = blockIdx.x;
    int b = r / NFL, f = r - b * NFL;
    const float* src; const float* w; const float* bias;
    bool is_lat = (f >= NF);
    int ql = 0;
    if (!is_lat) { src = feat + (size_t)(b * NF + f) * ND; w = lnm_w; bias = lnm_b; }
    else { ql = f - NF; src = lat + (size_t)(b * NQ + ql) * ND; w = lnl_w; bias = lnl_b; }

    int t = threadIdx.x;
    float4 v = ((const float4*)src)[t];
    float s  = v.x + v.y + v.z + v.w;
    float ss = v.x*v.x + v.y*v.y + v.z*v.z + v.w*v.w;

    __shared__ float red[2][8];
    __shared__ float stat[2];
    #pragma unroll
    for (int o = 16; o > 0; o >>= 1) {
        s  += __shfl_down_sync(0xffffffffu, s,  o);
        ss += __shfl_down_sync(0xffffffffu, ss, o);
    }
    int wid = t >> 5, lid = t & 31;
    if (lid == 0) { red[0][wid] = s; red[1][wid] = ss; }
    __syncthreads();
    if (t == 0) {
        float a = 0.f, c = 0.f;
        #pragma unroll
        for (int i = 0; i < 8; i++) { a += red[0][i]; c += red[1][i]; }
        float mu  = a * (1.0f / ND);
        float var = c * (1.0f / ND) - mu * mu;
        stat[0] = mu; stat[1] = rsqrtf(var + 1e-5f);
    }
    __syncthreads();
    float mu = stat[0], inv = stat[1];
    float4 w4 = ((const float4*)w)[t];
    float4 b4 = ((const float4*)bias)[t];
    float o0 = (v.x - mu) * inv * w4.x + b4.x;
    float o1 = (v.y - mu) * inv * w4.y + b4.y;
    float o2 = (v.z - mu) * inv * w4.z + b4.z;
    float o3 = (v.w - mu) * inv * w4.w + b4.w;

    __nv_bfloat16 h0 = __float2bfloat16(o0), h1 = __float2bfloat16(o1);
    __nv_bfloat16 h2 = __float2bfloat16(o2), h3 = __float2bfloat16(o3);
    __nv_bfloat16 l0 = __float2bfloat16(o0 - __bfloat162float(h0));
    __nv_bfloat16 l1 = __float2bfloat16(o1 - __bfloat162float(h1));
    __nv_bfloat16 l2 = __float2bfloat16(o2 - __bfloat162float(h2));
    __nv_bfloat16 l3 = __float2bfloat16(o3 - __bfloat162float(h3));

    size_t idx = (size_t)r * ND + t * 4;
    *(__nv_bfloat162*)&g_xh[idx]     = __nv_bfloat162{h0, h1};
    *(__nv_bfloat162*)&g_xh[idx + 2] = __nv_bfloat162{h2, h3};
    *(__nv_bfloat162*)&g_xl[idx]     = __nv_bfloat162{l0, l1};
    *(__nv_bfloat162*)&g_xl[idx + 2] = __nv_bfloat162{l2, l3};
    if (is_lat) {
        size_t li = (size_t)(b * NQ + ql) * ND + t * 4;
        *(__nv_bfloat162*)&g_lath[li]     = __nv_bfloat162{h0, h1};
        *(__nv_bfloat162*)&g_lath[li + 2] = __nv_bfloat162{h2, h3};
        *(__nv_bfloat162*)&g_latl[li]     = __nv_bfloat162{l0, l1};
        *(__nv_bfloat162*)&g_latl[li + 2] = __nv_bfloat162{l2, l3};
    }
}

// ============ weight transpose + hi/lo split: W[K,N] -> T{hi,lo}[N,K] ======
__global__ __launch_bounds__(256) void wsplit_kernel(
    const float* __restrict__ W, __nv_bfloat16* __restrict__ Th,
    __nv_bfloat16* __restrict__ Tl)
{
    __shared__ float t[32][33];
    int bx = blockIdx.x * 32;
    int by = blockIdx.y * 32;
    int tx = threadIdx.x & 31, ty = threadIdx.x >> 5;
    #pragma unroll
    for (int i = 0; i < 32; i += 8)
        t[ty + i][tx] = W[(size_t)(by + ty + i) * 1024 + bx + tx];
    __syncthreads();
    #pragma unroll
    for (int i = 0; i < 32; i += 8) {
        float v = t[tx][ty + i];
        __nv_bfloat16 h = __float2bfloat16(v);
        __nv_bfloat16 l = __float2bfloat16(v - __bfloat162float(h));
        size_t o = (size_t)(bx + ty + i) * 1024 + by + tx;
        Th[o] = h; Tl[o] = l;
    }
}

// ==================== bf16 split GEMM on mma.sync (Q / O projections) ======
#define LDT 40
#define VHALVES (128 * LDT)
#define STGH (4 * VHALVES)
#define GEMM_SMEM_BYTES (2 * STGH * 2)   // 81920

__device__ __forceinline__ void cp_var(uint32_t sb, uint32_t dsth,
                                       const __nv_bfloat16* __restrict__ src,
                                       int row0, int kt, int tid)
{
    #pragma unroll
    for (int j = 0; j < 2; j++) {
        int ci = tid + j * 256;
        int row = ci >> 2, c = ci & 3;
        uint32_t so = sb + (dsth + row * LDT + c * 8) * 2;
        const __nv_bfloat16* gp = src + (size_t)(row0 + row) * 1024 + kt * 32 + c * 8;
        asm volatile("cp.async.cg.shared.global [%0], [%1], 16;" :: "r"(so), "l"(gp));
    }
}

__global__ __launch_bounds__(256)
void gemm_mma_kernel(const __nv_bfloat16* __restrict__ Ah, const __nv_bfloat16* __restrict__ Al,
                     const __nv_bfloat16* __restrict__ Bh, const __nv_bfloat16* __restrict__ Bl,
                     float* __restrict__ Cf, __nv_bfloat16* __restrict__ Ch,
                     __nv_bfloat16* __restrict__ Cl, float alpha)
{
    extern __shared__ __nv_bfloat16 smn[];
    uint32_t sb = smem_u32(smn);
    int tid = threadIdx.x;
    int lid = tid & 31;
    int wid = tid >> 5;
    int warp_m = wid >> 2;
    int warp_n = wid & 3;
    int bm = blockIdx.y * 128;
    int bn = blockIdx.x * 128;

    float acc[4][4][4];
    #pragma unroll
    for (int i = 0; i < 4; i++)
        #pragma unroll
        for (int j = 0; j < 4; j++)
            #pragma unroll
            for (int k = 0; k < 4; k++) acc[i][j][k] = 0.f;

    const int NT = 32;
    {
        uint32_t st = 0;
        cp_var(sb, st,               Ah, bm, 0, tid);
        cp_var(sb, st + VHALVES,     Al, bm, 0, tid);
        cp_var(sb, st + 2 * VHALVES, Bh, bn, 0, tid);
        cp_var(sb, st + 3 * VHALVES, Bl, bn, 0, tid);
        asm volatile("cp.async.commit_group;" ::: "memory");
    }
    int a_row = lid & 15, a_koff = (lid >> 4) * 8;
    int b_row = lid & 7,  b_koff = ((lid >> 3) & 1) * 8;

    for (int kt = 0; kt < NT; ++kt) {
        if (kt + 1 < NT) {
            uint32_t st = ((kt + 1) & 1) * STGH;
            cp_var(sb, st,               Ah, bm, kt + 1, tid);
            cp_var(sb, st + VHALVES,     Al, bm, kt + 1, tid);
            cp_var(sb, st + 2 * VHALVES, Bh, bn, kt + 1, tid);
            cp_var(sb, st + 3 * VHALVES, Bl, bn, kt + 1, tid);
            asm volatile("cp.async.commit_group;" ::: "memory");
            asm volatile("cp.async.wait_group 1;" ::: "memory");
        } else {
            asm volatile("cp.async.wait_group 0;" ::: "memory");
        }
        __syncthreads();

        uint32_t st = (kt & 1) * STGH;
        uint32_t Ah_b = sb + (st) * 2;
        uint32_t Al_b = sb + (st + VHALVES) * 2;
        uint32_t Bh_b = sb + (st + 2 * VHALVES) * 2;
        uint32_t Bl_b = sb + (st + 3 * VHALVES) * 2;

        #pragma unroll
        for (int ks = 0; ks < 2; ++ks) {
            uint32_t ah[4][4], al[4][4], bf[4][2];
            #pragma unroll
            for (int mt = 0; mt < 4; mt++) {
                uint32_t off = ((warp_m * 64 + mt * 16 + a_row) * LDT + ks * 16 + a_koff) * 2;
                ldm_x4(ah[mt], Ah_b + off);
            }
            #pragma unroll
            for (int nt = 0; nt < 4; nt++) {
                uint32_t off = ((warp_n * 32 + nt * 8 + b_row) * LDT + ks * 16 + b_koff) * 2;
                ldm_x2(bf[nt], Bh_b + off);
            }
            #pragma unroll
            for (int mt = 0; mt < 4; mt++)
                #pragma unroll
                for (int nt = 0; nt < 4; nt++) mma_bf16(acc[mt][nt], ah[mt], bf[nt]);
            #pragma unroll
            for (int mt = 0; mt < 4; mt++) {
                uint32_t off = ((warp_m * 64 + mt * 16 + a_row) * LDT + ks * 16 + a_koff) * 2;
                ldm_x4(al[mt], Al_b + off);
            }
            #pragma unroll
            for (int mt = 0; mt < 4; mt++)
                #pragma unroll
                for (int nt = 0; nt < 4; nt++) mma_bf16(acc[mt][nt], al[mt], bf[nt]);
            #pragma unroll
            for (int nt = 0; nt < 4; nt++) {
                uint32_t off = ((warp_n * 32 + nt * 8 + b_row) * LDT + ks * 16 + b_koff) * 2;
                ldm_x2(bf[nt], Bl_b + off);
            }
            #pragma unroll
            for (int mt = 0; mt < 4; mt++)
                #pragma unroll
                for (int nt = 0; nt < 4; nt++) mma_bf16(acc[mt][nt], ah[mt], bf[nt]);
        }
        __syncthreads();
    }

    int r0 = bm + warp_m * 64 + (lid >> 2);
    int c0 = bn + warp_n * 32 + (lid & 3) * 2;
    if (Cf) {
        #pragma unroll
        for (int mt = 0; mt < 4; mt++) {
            #pragma unroll
            for (int nt = 0; nt < 4; nt++) {
                float* p0 = Cf + (size_t)(r0 + mt * 16) * 1024 + c0 + nt * 8;
                float* p1 = Cf + (size_t)(r0 + mt * 16 + 8) * 1024 + c0 + nt * 8;
                *(float2*)p0 = make_float2(alpha * acc[mt][nt][0], alpha * acc[mt][nt][1]);
                *(float2*)p1 = make_float2(alpha * acc[mt][nt][2], alpha * acc[mt][nt][3]);
            }
        }
    } else {
        #pragma unroll
        for (int mt = 0; mt < 4; mt++) {
            #pragma unroll
            for (int nt = 0; nt < 4; nt++) {
                #pragma unroll
                for (int half = 0; half < 2; half++) {
                    float v0 = alpha * acc[mt][nt][half * 2];
                    float v1 = alpha * acc[mt][nt][half * 2 + 1];
                    __nv_bfloat16 h0 = __float2bfloat16(v0), h1 = __float2bfloat16(v1);
                    __nv_bfloat16 l0 = __float2bfloat16(v0 - __bfloat162float(h0));
                    __nv_bfloat16 l1 = __float2bfloat16(v1 - __bfloat162float(h1));
                    size_t o = (size_t)(r0 + mt * 16 + half * 8) * 1024 + c0 + nt * 8;
                    *(__nv_bfloat162*)&Ch[o] = __nv_bfloat162{h0, h1};
                    *(__nv_bfloat162*)&Cl[o] = __nv_bfloat162{l0, l1};
                }
            }
        }
    }
}

// ============ fused K+V projection: shared A, 3-stage pipeline =============
#define FLDT 40
#define FVH (128 * FLDT)              // 5120 halves per tile
#define FSTGH (6 * FVH)               // 30720 halves per stage (Ah,Al,Bkh,Bkl,Bvh,Bvl)
#define FSTAGES 3
#define FUSED_SMEM_BYTES (FSTAGES * FSTGH * 2)   // 184320

__device__ __forceinline__ void cp_stage6(uint32_t sb, int slot,
    const __nv_bfloat16* __restrict__ Ah, const __nv_bfloat16* __restrict__ Al,
    const __nv_bfloat16* __restrict__ Bkh, const __nv_bfloat16* __restrict__ Bkl,
    const __nv_bfloat16* __restrict__ Bvh, const __nv_bfloat16* __restrict__ Bvl,
    int bm, int bn, int kt, int tid)
{
    uint32_t base = sb + slot * FSTGH * 2;
    #pragma unroll
    for (int t6 = 0; t6 < 6; t6++) {
        const __nv_bfloat16* src =
            (t6 == 0) ? Ah : (t6 == 1) ? Al : (t6 == 2) ? Bkh :
            (t6 == 3) ? Bkl : (t6 == 4) ? Bvh : Bvl;
        int r0 = (t6 < 2) ? bm : bn;
        #pragma unroll
        for (int u = 0; u < 2; u++) {
            int idx = tid + u * 256;          // 0..511
            int row = idx >> 2, c = idx & 3;
            uint32_t dst = base + (t6 * FVH + row * FLDT + c * 8) * 2;
            const __nv_bfloat16* gp = src + (size_t)(r0 + row) * 1024 + kt * 32 + c * 8;
            asm volatile("cp.async.cg.shared.global [%0], [%1], 16;" :: "r"(dst), "l"(gp));
        }
    }
}

__global__ __launch_bounds__(256, 1)
void gemm_kv_fused_kernel(const __nv_bfloat16* __restrict__ Ah, const __nv_bfloat16* __restrict__ Al,
                          const __nv_bfloat16* __restrict__ Bkh, const __nv_bfloat16* __restrict__ Bkl,
                          const __nv_bfloat16* __restrict__ Bvh, const __nv_bfloat16* __restrict__ Bvl,
                          __nv_bfloat16* __restrict__ Kh, __nv_bfloat16* __restrict__ Kl,
                          __nv_bfloat16* __restrict__ Vh, __nv_bfloat16* __restrict__ Vl)
{
    extern __shared__ __nv_bfloat16 smn[];
    uint32_t sb = smem_u32(smn);
    int tid = threadIdx.x;
    int lid = tid & 31;
    int wid = tid >> 5;
    int warp_m = wid >> 2;            // 0..1
    int warp_n = wid & 3;             // 0..3
    int bm = blockIdx.y * 128;
    int bn = blockIdx.x * 128;

    float aK[4][4][4], aV[4][4][4];
    #pragma unroll
    for (int i = 0; i < 4; i++)
        #pragma unroll
        for (int j = 0; j < 4; j++)
            #pragma unroll
            for (int k = 0; k < 4; k++) { aK[i][j][k] = 0.f; aV[i][j][k] = 0.f; }

    const int NT = 32;
    // prologue: stages 0, 1
    cp_stage6(sb, 0, Ah, Al, Bkh, Bkl, Bvh, Bvl, bm, bn, 0, tid);
    asm volatile("cp.async.commit_group;" ::: "memory");
    cp_stage6(sb, 1, Ah, Al, Bkh, Bkl, Bvh, Bvl, bm, bn, 1, tid);
    asm volatile("cp.async.commit_group;" ::: "memory");

    int a_row = lid & 15, a_koff = (lid >> 4) * 8;
    int b_row = lid & 7,  b_koff = ((lid >> 3) & 1) * 8;

    for (int kt = 0; kt < NT; ++kt) {
        if (kt + 1 < NT) asm volatile("cp.async.wait_group 1;" ::: "memory");
        else             asm volatile("cp.async.wait_group 0;" ::: "memory");
        __syncthreads();
        if (kt + 2 < NT) {
            cp_stage6(sb, (kt + 2) % FSTAGES, Ah, Al, Bkh, Bkl, Bvh, Bvl,
                      bm, bn, kt + 2, tid);
            asm volatile("cp.async.commit_group;" ::: "memory");
        }

        uint32_t tb   = sb + (kt % FSTAGES) * FSTGH * 2;
        uint32_t Ahb  = tb;
        uint32_t Alb  = tb + FVH * 2;
        uint32_t Bkhb = tb + 2 * FVH * 2;
        uint32_t Bklb = tb + 3 * FVH * 2;
        uint32_t Bvhb = tb + 4 * FVH * 2;
        uint32_t Bvlb = tb + 5 * FVH * 2;

        #pragma unroll
        for (int ks = 0; ks < 2; ++ks) {
            uint32_t ah[4][4], al[4][4], bf[4][2];
            #pragma unroll
            for (int mt = 0; mt < 4; mt++) {
                uint32_t off = ((warp_m * 64 + mt * 16 + a_row) * FLDT + ks * 16 + a_koff) * 2;
                ldm_x4(ah[mt], Ahb + off);
                ldm_x4(al[mt], Alb + off);
            }
            uint32_t bo[4];
            #pragma unroll
            for (int nt = 0; nt < 4; nt++)
                bo[nt] = ((warp_n * 32 + nt * 8 + b_row) * FLDT + ks * 16 + b_koff) * 2;

            // ---- K: hi terms ----
            #pragma unroll
            for (int nt = 0; nt < 4; nt++) ldm_x2(bf[nt], Bkhb + bo[nt]);
            #pragma unroll
            for (int mt = 0; mt < 4; mt++)
                #pragma unroll
                for (int nt = 0; nt < 4; nt++) {
                    mma_bf16(aK[mt][nt], ah[mt], bf[nt]);
                    mma_bf16(aK[mt][nt], al[mt], bf[nt]);
                }
            // ---- K: lo term ----
            #pragma unroll
            for (int nt = 0; nt < 4; nt++) ldm_x2(bf[nt], Bklb + bo[nt]);
            #pragma unroll
            for (int mt = 0; mt < 4; mt++)
                #pragma unroll
                for (int nt = 0; nt < 4; nt++) mma_bf16(aK[mt][nt], ah[mt], bf[nt]);
            // ---- V: hi terms ----
            #pragma unroll
            for (int nt = 0; nt < 4; nt++) ldm_x2(bf[nt], Bvhb + bo[nt]);
            #pragma unroll
            for (int mt = 0; mt < 4; mt++)
                #pragma unroll
                for (int nt = 0; nt < 4; nt++) {
                    mma_bf16(aV[mt][nt], ah[mt], bf[nt]);
                    mma_bf16(aV[mt][nt], al[mt], bf[nt]);
                }
            // ---- V: lo term ----
            #pragma unroll
            for (int nt = 0; nt < 4; nt++) ldm_x2(bf[nt], Bvlb + bo[nt]);
            #pragma unroll
            for (int mt = 0; mt < 4; mt++)
                #pragma unroll
                for (int nt = 0; nt < 4; nt++) mma_bf16(aV[mt][nt], ah[mt], bf[nt]);
        }
    }

    // epilogue: hi/lo bf16 for K and V
    int r0 = bm + warp_m * 64 + (lid >> 2);
    int c0 = bn + warp_n * 32 + (lid & 3) * 2;
    #pragma unroll
    for (int mt = 0; mt < 4; mt++) {
        #pragma unroll
        for (int nt = 0; nt < 4; nt++) {
            #pragma unroll
            for (int half = 0; half < 2; half++) {
                size_t o = (size_t)(r0 + mt * 16 + half * 8) * 1024 + c0 + nt * 8;
                {
                    float v0 = aK[mt][nt][half * 2], v1 = aK[mt][nt][half * 2 + 1];
                    __nv_bfloat16 h0 = __float2bfloat16(v0), h1 = __float2bfloat16(v1);
                    __nv_bfloat16 l0 = __float2bfloat16(v0 - __bfloat162float(h0));
                    __nv_bfloat16 l1 = __float2bfloat16(v1 - __bfloat162float(h1));
                    *(__nv_bfloat162*)&Kh[o] = __nv_bfloat162{h0, h1};
                    *(__nv_bfloat162*)&Kl[o] = __nv_bfloat162{l0, l1};
                }
                {
                    float v0 = aV[mt][nt][half * 2], v1 = aV[mt][nt][half * 2 + 1];
                    __nv_bfloat16 h0 = __float2bfloat16(v0), h1 = __float2bfloat16(v1);
                    __nv_bfloat16 l0 = __float2bfloat16(v0 - __bfloat162float(h0));
                    __nv_bfloat16 l1 = __float2bfloat16(v1 - __bfloat162float(h1));
                    *(__nv_bfloat162*)&Vh[o] = __nv_bfloat162{h0, h1};
                    *(__nv_bfloat162*)&Vl[o] = __nv_bfloat162{l0, l1};
                }
            }
        }
    }
}

// ==================== tensor-core flash attention, split-KV=4 ==============
#define NSPLIT 4
#define CPS 17
#define ASTR 72                       // padded row stride (halves)
#define QTILE (64 * ASTR)             // 4608 halves per tile variant
#define ATTN_SMEM ((2 * QTILE + 2 * 4 * QTILE) * 2)   // 92160 bytes

__device__ __forceinline__ void stage_kv(uint32_t sb, uint32_t stbase,
    const __nv_bfloat16* kh, const __nv_bfloat16* kl,
    const __nv_bfloat16* vh, const __nv_bfloat16* vl, size_t off, int tid)
{
    const __nv_bfloat16* srcs[4] = {kh, kl, vh, vl};
    #pragma unroll
    for (int j = 0; j < 16; j++) {
        int ci = tid + j * 128;               // 0..2047
        int tile = ci >> 9, row = (ci >> 3) & 63, c = ci & 7;
        uint32_t dst = sb + (stbase + tile * QTILE + row * ASTR) * 2 + c * 16;
        const __nv_bfloat16* src = srcs[tile] + off + (size_t)row * INNER + c * 8;
        asm volatile("cp.async.cg.shared.global [%0], [%1], 16;" :: "r"(dst), "l"(src));
    }
}

__global__ __launch_bounds__(128) void attn_kernel()
{
    extern __shared__ __nv_bfloat16 asmem[];
    uint32_t sb = smem_u32(asmem);
    const uint32_t QH = 0, QL = QTILE, ST0 = 2 * QTILE;

    int tid = threadIdx.x, lid = tid & 31, wid = tid >> 5;
    int bh = blockIdx.x, b = bh >> 4, h = bh & 15;
    int sp = blockIdx.y;
    int c0 = sp * CPS, c1 = min(65, c0 + CPS);

    const __nv_bfloat16* qhg = g_qh + (size_t)(b * NQ) * INNER + h * DHD;
    const __nv_bfloat16* qlg = g_ql + (size_t)(b * NQ) * INNER + h * DHD;
    const __nv_bfloat16* khg = g_kh + (size_t)(b * NFL) * INNER + h * DHD;
    const __nv_bfloat16* klg = g_kl + (size_t)(b * NFL) * INNER + h * DHD;
    const __nv_bfloat16* vhg = g_vh + (size_t)(b * NFL) * INNER + h * DHD;
    const __nv_bfloat16* vlg = g_vl + (size_t)(b * NFL) * INNER + h * DHD;

    #pragma unroll
    for (int j = 0; j < 8; j++) {
        int ci = tid + j * 128;               // 0..1023
        int tile = ci >> 9, row = (ci >> 3) & 63, c = ci & 7;
        uint32_t dst = sb + ((tile ? QL : QH) + row * ASTR) * 2 + c * 16;
        const __nv_bfloat16* src = (tile ? qlg : qhg) + (size_t)row * INNER + c * 8;
        asm volatile("cp.async.cg.shared.global [%0], [%1], 16;" :: "r"(dst), "l"(src));
    }
    stage_kv(sb, ST0, khg, klg, vhg, vlg, (size_t)c0 * 64 * INNER, tid);
    asm volatile("cp.async.commit_group;" ::: "memory");

    float oc[8][4];
    #pragma unroll
    for (int i = 0; i < 8; i++)
        #pragma unroll
        for (int j = 0; j < 4; j++) oc[i][j] = 0.f;
    float m0 = -1e30f, m1 = -1e30f, l0 = 0.f, l1 = 0.f;

    uint32_t qhf[4][4], qlf[4][4];
    bool qloaded = false;

    for (int c = c0; c < c1; ++c) {
        int p = (c - c0) & 1;
        if (c + 1 < c1) {
            stage_kv(sb, ST0 + (1 - p) * 4 * QTILE, khg, klg, vhg, vlg,
                     (size_t)(c + 1) * 64 * INNER, tid);
            asm volatile("cp.async.commit_group;" ::: "memory");
            asm volatile("cp.async.wait_group 1;" ::: "memory");
        } else {
            asm volatile("cp.async.wait_group 0;" ::: "memory");
        }
        __syncthreads();

        if (!qloaded) {
            #pragma unroll
            for (int t = 0; t < 4; t++) {
                uint32_t ao = ((wid * 16 + (lid & 15)) * ASTR + t * 16 + (lid >> 4) * 8) * 2;
                ldm_x4(qhf[t], sb + QH * 2 + ao);
                ldm_x4(qlf[t], sb + QL * 2 + ao);
            }
            qloaded = true;
        }
        uint32_t stb = ST0 + p * 4 * QTILE;

        float sc[8][4];
        #pragma unroll
        for (int j = 0; j < 8; j++)
            #pragma unroll
            for (int k = 0; k < 4; k++) sc[j][k] = 0.f;
        #pragma unroll
        for (int t = 0; t < 4; t++) {
            #pragma unroll
            for (int j = 0; j < 8; j++) {
                uint32_t ko = ((8 * j + (lid & 7)) * ASTR + t * 16 + ((lid >> 3) & 1) * 8) * 2;
                uint32_t bK[2], bKl[2];
                ldm_x2(bK,  sb + stb * 2 + ko);
                ldm_x2(bKl, sb + (stb + QTILE) * 2 + ko);
                mma_bf16(sc[j], qhf[t], bK);
                mma_bf16(sc[j], qlf[t], bK);
                mma_bf16(sc[j], qhf[t], bKl);
            }
        }
        float cm0 = -1e30f, cm1 = -1e30f;
        #pragma unroll
        for (int j = 0; j < 8; j++) {
            cm0 = fmaxf(cm0, fmaxf(sc[j][0], sc[j][1]));
            cm1 = fmaxf(cm1, fmaxf(sc[j][2], sc[j][3]));
        }
        cm0 = fmaxf(cm0, __shfl_xor_sync(0xffffffffu, cm0, 1));
        cm0 = fmaxf(cm0, __shfl_xor_sync(0xffffffffu, cm0, 2));
        cm1 = fmaxf(cm1, __shfl_xor_sync(0xffffffffu, cm1, 1));
        cm1 = fmaxf(cm1, __shfl_xor_sync(0xffffffffu, cm1, 2));
        float nm0 = fmaxf(m0, cm0), nm1 = fmaxf(m1, cm1);
        float sum0 = 0.f, sum1 = 0.f;
        #pragma unroll
        for (int j = 0; j < 8; j++) {
            sc[j][0] = __expf(sc[j][0] - nm0);
            sc[j][1] = __expf(sc[j][1] - nm0);
            sc[j][2] = __expf(sc[j][2] - nm1);
            sc[j][3] = __expf(sc[j][3] - nm1);
            sum0 += sc[j][0] + sc[j][1];
            sum1 += sc[j][2] + sc[j][3];
        }
        sum0 += __shfl_xor_sync(0xffffffffu, sum0, 1);
        sum0 += __shfl_xor_sync(0xffffffffu, sum0, 2);
        sum1 += __shfl_xor_sync(0xffffffffu, sum1, 1);
        sum1 += __shfl_xor_sync(0xffffffffu, sum1, 2);
        float e0 = __expf(m0 - nm0), e1 = __expf(m1 - nm1);
        l0 = l0 * e0 + sum0; l1 = l1 * e1 + sum1;
        m0 = nm0; m1 = nm1;
        #pragma unroll
        for (int nd = 0; nd < 8; nd++) {
            oc[nd][0] *= e0; oc[nd][1] *= e0;
            oc[nd][2] *= e1; oc[nd][3] *= e1;
        }
        uint32_t vstb = stb + 2 * QTILE;
        #pragma unroll
        for (int t2 = 0; t2 < 4; t2++) {
            float ph[8], pl[8];
            #pragma unroll
            for (int u = 0; u < 2; u++) {
                #pragma unroll
                for (int k = 0; k < 4; k++) {
                    float v = sc[2 * t2 + u][k];
                    __nv_bfloat16 hb = __float2bfloat16(v);
                    float hf = __bfloat162float(hb);
                    ph[u * 4 + k] = hf;
                    pl[u * 4 + k] = v - hf;
                }
            }
            uint32_t aph[4], apl[4];
            aph[0] = packbf(ph[0], ph[1]); aph[1] = packbf(ph[2], ph[3]);
            aph[2] = packbf(ph[4], ph[5]); aph[3] = packbf(ph[6], ph[7]);
            apl[0] = packbf(pl[0], pl[1]); apl[1] = packbf(pl[2], pl[3]);
            apl[2] = packbf(pl[4], pl[5]); apl[3] = packbf(pl[6], pl[7]);
            #pragma unroll
            for (int nd = 0; nd < 8; nd++) {
                uint32_t vo = ((16 * t2 + (lid & 15)) * ASTR + nd * 8) * 2;
                uint32_t bV[2], bVl[2];
                ldm_x2_t(bV,  sb + vstb * 2 + vo);
                ldm_x2_t(bVl, sb + (vstb + QTILE) * 2 + vo);
                mma_bf16(oc[nd], aph, bV);
                mma_bf16(oc[nd], apl, bV);
                mma_bf16(oc[nd], aph, bVl);
            }
        }
        __syncthreads();
    }
    float i0 = 1.0f / l0, i1 = 1.0f / l1;
    int pidx = bh * NSPLIT + sp;
    int r0 = wid * 16 + (lid >> 2), r1 = r0 + 8;
    #pragma unroll
    for (int nd = 0; nd < 8; nd++) {
        int col = 8 * nd + (lid & 3) * 2;
        *(float2*)&g_opart[((size_t)pidx * 64 + r0) * 64 + col] =
            make_float2(oc[nd][0] * i0, oc[nd][1] * i0);
        *(float2*)&g_opart[((size_t)pidx * 64 + r1) * 64 + col] =
            make_float2(oc[nd][2] * i1, oc[nd][3] * i1);
    }
    if ((lid & 3) == 0) {
        g_mpart[pidx * 64 + r0] = m0; g_lpart[pidx * 64 + r0] = l0;
        g_mpart[pidx * 64 + r1] = m1; g_lpart[pidx * 64 + r1] = l1;
    }
}

// ---------------- merge splits -> attn out hi/lo ---------------------------
__global__ __launch_bounds__(256) void attn_merge_kernel()
{
    int bh = blockIdx.x;
    int b = bh >> 4, h = bh & 15;
    int row = threadIdx.x >> 2;
    int cg  = threadIdx.x & 3;
    float m[NSPLIT], l[NSPLIT];
    #pragma unroll
    for (int s = 0; s < NSPLIT; s++) {
        m[s] = g_mpart[(bh * NSPLIT + s) * 64 + row];
        l[s] = g_lpart[(bh * NSPLIT + s) * 64 + row];
    }
    float M = m[0];
    #pragma unroll
    for (int s = 1; s < NSPLIT; s++) M = fmaxf(M, m[s]);
    float w[NSPLIT]; float L = 0.f;
    #pragma unroll
    for (int s = 0; s < NSPLIT; s++) { w[s] = __expf(m[s] - M); L += w[s] * l[s]; }
    float inv = 1.0f / L;
    #pragma unroll
    for (int j = 0; j < 16; j++) {
        int col = cg * 16 + j;
        float acc = 0.f;
        #pragma unroll
        for (int s = 0; s < NSPLIT; s++)
            acc += g_opart[((size_t)(bh * NSPLIT + s) * 64 + row) * 64 + col] * w[s] * l[s];
        acc *= inv;
        __nv_bfloat16 hh = __float2bfloat16(acc);
        size_t oidx = (size_t)(b * NQ + row) * INNER + h * DHD + col;
        g_ah[oidx] = hh;
        g_al[oidx] = __float2bfloat16(acc - __bfloat162float(hh));
    }
}

// ==================== launcher =============================================
extern "C" void kernel_launch(void* const* d_in, const int* in_sizes, int n_in,
                              void* d_out, int out_size)
{
    const float* features = (const float*)d_in[0];
    const float* latents  = (const float*)d_in[1];
    const float* lnm_w    = (const float*)d_in[2];
    const float* lnm_b    = (const float*)d_in[3];
    const float* lnl_w    = (const float*)d_in[4];
    const float* lnl_b    = (const float*)d_in[5];
    const float* Wq       = (const float*)d_in[6];
    const float* Wk       = (const float*)d_in[7];
    const float* Wv       = (const float*)d_in[8];
    const float* Wo       = (const float*)d_in[9];
    float* out = (float*)d_out;

    __nv_bfloat16 *p_xh, *p_xl, *p_lath, *p_latl;
    __nv_bfloat16 *p_wqh, *p_wql, *p_wkh, *p_wkl, *p_wvh, *p_wvl, *p_woh, *p_wol;
    __nv_bfloat16 *p_ah, *p_al, *p_qh, *p_ql, *p_kh, *p_kl, *p_vh, *p_vl;
    cudaGetSymbolAddress((void**)&p_xh, g_xh);   cudaGetSymbolAddress((void**)&p_xl, g_xl);
    cudaGetSymbolAddress((void**)&p_lath, g_lath); cudaGetSymbolAddress((void**)&p_latl, g_latl);
    cudaGetSymbolAddress((void**)&p_wqh, g_wqh); cudaGetSymbolAddress((void**)&p_wql, g_wql);
    cudaGetSymbolAddress((void**)&p_wkh, g_wkh); cudaGetSymbolAddress((void**)&p_wkl, g_wkl);
    cudaGetSymbolAddress((void**)&p_wvh, g_wvh); cudaGetSymbolAddress((void**)&p_wvl, g_wvl);
    cudaGetSymbolAddress((void**)&p_woh, g_woh); cudaGetSymbolAddress((void**)&p_wol, g_wol);
    cudaGetSymbolAddress((void**)&p_ah, g_ah);   cudaGetSymbolAddress((void**)&p_al, g_al);
    cudaGetSymbolAddress((void**)&p_qh, g_qh);   cudaGetSymbolAddress((void**)&p_ql, g_ql);
    cudaGetSymbolAddress((void**)&p_kh, g_kh);   cudaGetSymbolAddress((void**)&p_kl, g_kl);
    cudaGetSymbolAddress((void**)&p_vh, g_vh);   cudaGetSymbolAddress((void**)&p_vl, g_vl);

    cudaFuncSetAttribute(gemm_mma_kernel,
                         cudaFuncAttributeMaxDynamicSharedMemorySize, GEMM_SMEM_BYTES);
    cudaFuncSetAttribute(gemm_kv_fused_kernel,
                         cudaFuncAttributeMaxDynamicSharedMemorySize, FUSED_SMEM_BYTES);
    cudaFuncSetAttribute(attn_kernel,
                         cudaFuncAttributeMaxDynamicSharedMemorySize, ATTN_SMEM);

    // 1) LayerNorm -> bf16 hi/lo
    ln_kernel<<<NB * NFL, 256>>>(features, latents, lnm_w, lnm_b, lnl_w, lnl_b);

    // 2) weight transpose + split
    dim3 gW(32, 32);
    wsplit_kernel<<<gW, 256>>>(Wq, p_wqh, p_wql);
    wsplit_kernel<<<gW, 256>>>(Wk, p_wkh, p_wkl);
    wsplit_kernel<<<gW, 256>>>(Wv, p_wvh, p_wvl);
    wsplit_kernel<<<gW, 256>>>(Wo, p_woh, p_wol);

    // 3) fused K+V projection (shared A, 3-stage pipeline)
    dim3 gKV(8, MKV / 128);
    gemm_kv_fused_kernel<<<gKV, 256, FUSED_SMEM_BYTES>>>(
        p_xh, p_xl, p_wkh, p_wkl, p_wvh, p_wvl, p_kh, p_kl, p_vh, p_vl);

    // 4) Q projection -> bf16 hi/lo (scale folded)
    dim3 gQ(8, MQ / 128);
    gemm_mma_kernel<<<gQ, 256, GEMM_SMEM_BYTES>>>(p_lath, p_latl, p_wqh, p_wql,
                                                  nullptr, p_qh, p_ql, 0.125f);

    // 5) tensor-core attention split-KV + merge
    dim3 gA(NB * NH, NSPLIT);
    attn_kernel<<<gA, 128, ATTN_SMEM>>>();
    attn_merge_kernel<<<NB * NH, 256>>>();

    // 6) output projection -> fp32 out
    gemm_mma_kernel<<<gQ, 256, GEMM_SMEM_BYTES>>>(p_ah, p_al, p_woh, p_wol,
                                                  out, nullptr, nullptr, 1.0f);
}